// round 7
// baseline (speedup 1.0000x reference)
#include <cuda_runtime.h>
#include <cuda_fp16.h>
#include <cstdint>

#define NL0 65536
#define NL1 16384
#define NL2 4096
#define NL3 1024
#define NL4 256
#define C   256

#define OFF4 0
#define OFF3 (NL4*C)
#define OFF2 (OFF3 + NL3*C)
#define OFF1 (OFF2 + NL2*C)
#define OFF0 (OFF1 + NL1*C)

// B pre-split (first 256 k only), fragment-major: [ch8][s2][ntg32][T32][reg2]
__device__ uint32_t g_Bh16[5][32768];
__device__ uint32_t g_Bl16[5][32768];
// ping-pong fp16 hi/lo images of pe levels (max 16384 rows x 128 words)
__device__ uint32_t g_H0[16384 * 128], g_L0[16384 * 128];
__device__ uint32_t g_H1[16384 * 128], g_L1[16384 * 128];
// per-level epilogue coefficients: [lvl][ WP(3) | WallP(3) | cvec ][256]
__device__ float g_coef[5][7 * 256];
__device__ float g_cls4[C];
__device__ float g_xyz1[NL1 * 3];
__device__ float g_xyz2[NL2 * 3];
__device__ float g_xyz3[NL3 * 3];
__device__ float g_xyz4[NL4 * 3];
__device__ int   g_k34[NL3];
__device__ int   g_k23[NL2];
__device__ int   g_k12[NL1];

__device__ __forceinline__ uint32_t smem_u32(const void* p) {
    uint32_t a;
    asm("{ .reg .u64 t; cvta.to.shared.u64 t, %1; cvt.u32.u64 %0, t; }" : "=r"(a) : "l"(p));
    return a;
}
__device__ __forceinline__ void splith(float v, __half& h, __half& l) {
    h = __float2half_rn(v);
    l = __float2half_rn(v - __half2float(h));
}
__device__ __forceinline__ uint32_t packh(__half a, __half b) {
    return (uint32_t)__half_as_ushort(a) | ((uint32_t)__half_as_ushort(b) << 16);
}
__device__ __forceinline__ void split_pair(float v0, float v1, uint32_t& h, uint32_t& l) {
    __half2 hh = __float22half2_rn(make_float2(v0, v1));
    float2 bk = __half22float2(hh);
    __half2 ll = __float22half2_rn(make_float2(v0 - bk.x, v1 - bk.y));
    h = *(uint32_t*)&hh; l = *(uint32_t*)&ll;
}
__device__ __forceinline__ void mma16(float* d, const uint32_t* a, const uint32_t* b) {
    asm volatile("mma.sync.aligned.m16n8k16.row.col.f32.f16.f16.f32 "
        "{%0,%1,%2,%3}, {%4,%5,%6,%7}, {%8,%9}, {%0,%1,%2,%3};"
        : "+f"(d[0]), "+f"(d[1]), "+f"(d[2]), "+f"(d[3])
        : "r"(a[0]), "r"(a[1]), "r"(a[2]), "r"(a[3]), "r"(b[0]), "r"(b[1]));
}
#define LDM4(r, a)                                                                  \
    asm volatile("ldmatrix.sync.aligned.m8n8.x4.shared.b16 {%0,%1,%2,%3}, [%4];"    \
        : "=r"((r)[0]), "=r"((r)[1]), "=r"((r)[2]), "=r"((r)[3]) : "r"(a))

// ---------- small kernels ----------
__global__ void gather_kernel(const float* __restrict__ xyz0, const int* __restrict__ idx,
                              float* __restrict__ out, int M) {
    int i = blockIdx.x * blockDim.x + threadIdx.x;
    if (i < M) {
        int s = idx[i];
        out[i*3+0] = xyz0[s*3+0]; out[i*3+1] = xyz0[s*3+1]; out[i*3+2] = xyz0[s*3+2];
    }
}
// B pre-split (k < 256 only): k = ch*32 + s*16 + (T&3)*2 + reg*8 ; n = ntg*8 + T/4
__global__ void prep_B(const float* __restrict__ P, uint32_t* __restrict__ Bh,
                       uint32_t* __restrict__ Bl) {
    int i = blockIdx.x * 256 + threadIdx.x;           // 32768
    int reg = i & 1, T = (i >> 1) & 31, ntg = (i >> 6) & 31, s = (i >> 11) & 1, ch = i >> 12;
    int k = ch*32 + s*16 + (T & 3)*2 + reg*8;
    int n = ntg*8 + (T >> 2);
    __half h0, l0, h1, l1;
    splith(P[k*C + n], h0, l0);
    splith(P[(k+1)*C + n], h1, l1);
    Bh[i] = packh(h0, h1);
    Bl[i] = packh(l0, l1);
}
__global__ void cls4_kernel(const float* __restrict__ xyz0, const float* __restrict__ W,
                            const float* __restrict__ b, float* __restrict__ cls4) {
    int t = threadIdx.x;
    float w0 = W[t], w1 = W[C+t], w2 = W[2*C+t], bb = b[t];
    float m = -3.4e38f;
    for (int i = 0; i < NL4; i++) {
        float v = fmaf(xyz0[i*3+0], w0, fmaf(xyz0[i*3+1], w1, fmaf(xyz0[i*3+2], w2, bb)));
        m = fmaxf(m, v);
    }
    cls4[t] = m;
}
// coef: WP = W@P1, WallP = Wall@P2, cvec = b@P1 + ball@P2 + pb (+ cls4@P1 for lvl4)
__global__ void prep_coef(const float* __restrict__ W, const float* __restrict__ b,
                          const float* __restrict__ Wall, const float* __restrict__ ball,
                          const float* __restrict__ P, const float* __restrict__ pb,
                          const float* __restrict__ cls4, int lvl4,
                          float* __restrict__ coef) {
    int n = threadIdx.x;
    float wp0=0, wp1=0, wp2=0, q0=0, q1=0, q2=0, cv=0;
    for (int c = 0; c < 256; c++) {
        float p1 = P[c*C + n], p2 = P[(256 + c)*C + n];
        wp0 = fmaf(W[c], p1, wp0);
        wp1 = fmaf(W[256 + c], p1, wp1);
        wp2 = fmaf(W[512 + c], p1, wp2);
        q0 = fmaf(Wall[c], p2, q0);
        q1 = fmaf(Wall[256 + c], p2, q1);
        q2 = fmaf(Wall[512 + c], p2, q2);
        float bc = b[c] + (lvl4 ? cls4[c] : 0.0f);
        cv = fmaf(bc, p1, fmaf(ball[c], p2, cv));
    }
    coef[0*256+n] = wp0; coef[1*256+n] = wp1; coef[2*256+n] = wp2;
    coef[3*256+n] = q0;  coef[4*256+n] = q1;  coef[5*256+n] = q2;
    coef[6*256+n] = cv + pb[n];
}
__global__ void nn_kernel(const float* __restrict__ q, const float* __restrict__ ref, int Mr,
                          int* __restrict__ out) {
    const int CH = 1024;
    __shared__ float rx[CH], ry[CH], rz[CH], rn[CH];
    int tid = blockIdx.x * blockDim.x + threadIdx.x;
    float qx = q[tid*3+0], qy = q[tid*3+1], qz = q[tid*3+2];
    float m2x = -2.f*qx, m2y = -2.f*qy, m2z = -2.f*qz;
    float best = 3.4e38f; int bi = 0;
    for (int base = 0; base < Mr; base += CH) {
        int n = min(CH, Mr - base);
        for (int j = threadIdx.x; j < n; j += blockDim.x) {
            float x = ref[(base+j)*3+0], y = ref[(base+j)*3+1], z = ref[(base+j)*3+2];
            rx[j]=x; ry[j]=y; rz[j]=z; rn[j] = x*x + y*y + z*z;
        }
        __syncthreads();
        #pragma unroll 8
        for (int j = 0; j < n; j++) {
            float d = fmaf(m2x, rx[j], fmaf(m2y, ry[j], fmaf(m2z, rz[j], rn[j])));
            if (d < best) { best = d; bi = base + j; }
        }
        __syncthreads();
    }
    out[tid] = bi;
}
// level 4: pure epilogue, 256 rows, no GEMM. Writes pe4 + its fp16 image.
__global__ void pe4_kernel(const float* __restrict__ xyzq, const float* __restrict__ xyz0,
                           const float* __restrict__ coef, float* __restrict__ out,
                           uint32_t* __restrict__ imgH, uint32_t* __restrict__ imgL) {
    int r = blockIdx.x, t = threadIdx.x;        // 128 threads, cols 2t, 2t+1
    float dx = xyzq[r*3+0], dy = xyzq[r*3+1], dz = xyzq[r*3+2];
    float x0 = xyz0[r*3+0], y0 = xyz0[r*3+1], z0 = xyz0[r*3+2];
    int c0 = 2*t;
    float v0 = coef[6*256+c0] + dx*coef[c0] + dy*coef[256+c0] + dz*coef[512+c0]
             + x0*coef[3*256+c0] + y0*coef[4*256+c0] + z0*coef[5*256+c0];
    int c1 = c0 + 1;
    float v1 = coef[6*256+c1] + dx*coef[c1] + dy*coef[256+c1] + dz*coef[512+c1]
             + x0*coef[3*256+c1] + y0*coef[4*256+c1] + z0*coef[5*256+c1];
    *(float2*)(out + (size_t)r*C + c0) = make_float2(v0, v1);
    uint32_t h, l; split_pair(v0, v1, h, l);
    imgH[r*128 + t] = h; imgL[r*128 + t] = l;
}

// ---------- pe GEMM: D = peImg[knn] @ P1 (fp16 3-pass) + rank-3 epilogue ----------
#define AL_OFF 2560
#define B_OFF  5120
#define BUFW   9216
#define SMEMB  (2 * BUFW * 4)

__global__ void __launch_bounds__(256, 2)
pe_mma(const int* __restrict__ knn,
       const float* __restrict__ xyzq, const float* __restrict__ xyzr,
       const float* __restrict__ xyz0,
       const uint32_t* __restrict__ srcH, const uint32_t* __restrict__ srcL,
       const uint32_t* __restrict__ Bh, const uint32_t* __restrict__ Bl,
       const float* __restrict__ coef, float* __restrict__ out,
       uint32_t* __restrict__ imgH, uint32_t* __restrict__ imgL, int write_img)
{
    extern __shared__ uint32_t sm[];
    __shared__ int s_knn[128];
    __shared__ float s_d[3][128], s_p[3][128];
    __shared__ float s_cf[7][128];

    const int t = threadIdx.x, lane = t & 31, wid = t >> 5;
    const int wm = wid & 3, wn = wid >> 2;
    const int rowbase = blockIdx.x * 128;
    const int yb = blockIdx.y;
    const uint32_t sbase = smem_u32(sm);

    if (t < 128) {
        int row = rowbase + t;
        int kk = knn[row];
        s_knn[t] = kk;
        s_d[0][t] = xyzq[row*3+0] - xyzr[kk*3+0];
        s_d[1][t] = xyzq[row*3+1] - xyzr[kk*3+1];
        s_d[2][t] = xyzq[row*3+2] - xyzr[kk*3+2];
        s_p[0][t] = xyz0[row*3+0];
        s_p[1][t] = xyz0[row*3+1];
        s_p[2][t] = xyz0[row*3+2];
    }
    {
        int j = t >> 7;                 // 0..1; cover 7 coef rows in 4 steps
        #pragma unroll
        for (int jj = j; jj < 7; jj += 2) s_cf[jj][t & 127] = coef[jj*256 + yb*128 + (t & 127)];
    }
    __syncthreads();

    const int arow = t & 127, ah2 = t >> 7;

    #define COPY_B(c) do {                                                             \
        const int bw_ = ((c) & 1) * BUFW;                                              \
        const uint32_t* s0_ = Bh + (size_t)(c)*4096 + yb*1024 + t*4;                   \
        const uint32_t* s1_ = Bl + (size_t)(c)*4096 + yb*1024 + t*4;                   \
        _Pragma("unroll")                                                              \
        for (int s_ = 0; s_ < 2; s_++) {                                               \
            asm volatile("cp.async.cg.shared.global [%0], [%1], 16;"                   \
                :: "r"(sbase + 4*(bw_ + B_OFF + s_*1024 + t*4)),                       \
                   "l"(s0_ + s_*2048) : "memory");                                     \
            asm volatile("cp.async.cg.shared.global [%0], [%1], 16;"                   \
                :: "r"(sbase + 4*(bw_ + B_OFF + 2048 + s_*1024 + t*4)),                \
                   "l"(s1_ + s_*2048) : "memory");                                     \
        }                                                                              \
    } while (0)

    #define FILL_A(c) do {                                                             \
        const int bw_ = ((c) & 1) * BUFW;                                              \
        const size_t so_ = (size_t)s_knn[arow]*128 + (c)*16 + ah2*8;                   \
        uint32_t d0_ = sbase + 4*(bw_ + arow*20 + ah2*8);                              \
        asm volatile("cp.async.cg.shared.global [%0], [%1], 16;"                       \
            :: "r"(d0_), "l"(srcH + so_) : "memory");                                  \
        asm volatile("cp.async.cg.shared.global [%0], [%1], 16;"                       \
            :: "r"(d0_ + 16), "l"(srcH + so_ + 4) : "memory");                         \
        asm volatile("cp.async.cg.shared.global [%0], [%1], 16;"                       \
            :: "r"(d0_ + AL_OFF*4), "l"(srcL + so_) : "memory");                       \
        asm volatile("cp.async.cg.shared.global [%0], [%1], 16;"                       \
            :: "r"(d0_ + AL_OFF*4 + 16), "l"(srcL + so_ + 4) : "memory");              \
    } while (0)

    float d[2][8][4];
    #pragma unroll
    for (int i = 0; i < 2; i++)
        #pragma unroll
        for (int j = 0; j < 8; j++)
            #pragma unroll
            for (int q = 0; q < 4; q++) d[i][j][q] = 0.0f;

    COPY_B(0);
    FILL_A(0);
    asm volatile("cp.async.commit_group;" ::: "memory");
    asm volatile("cp.async.wait_group 0;" ::: "memory");
    __syncthreads();

    const int r0 = lane >> 2, c0 = lane & 3;
    const int lr = (lane & 7) + ((lane >> 3) & 1) * 8;
    const int kseg = (lane >> 4) * 4;

    for (int c = 0; c < 8; c++) {
        if (c < 7) {
            COPY_B(c + 1);
            FILL_A(c + 1);
            asm volatile("cp.async.commit_group;" ::: "memory");
        }

        const int bw = (c & 1) * BUFW;
        #pragma unroll
        for (int s = 0; s < 2; s++) {
            uint32_t Afh[2][4], Afl[2][4];
            #pragma unroll
            for (int tmi = 0; tmi < 2; tmi++) {
                uint32_t aw = sbase + 4*(bw + (wm*32 + tmi*16 + lr)*20 + s*8 + kseg);
                LDM4(Afh[tmi], aw);
                LDM4(Afl[tmi], aw + AL_OFF*4);
            }
            uint32_t Bf[8][2];
            #pragma unroll
            for (int nt = 0; nt < 8; nt++) {
                int ntl = wn*8 + nt;
                *(uint2*)Bf[nt] = *(const uint2*)&sm[bw + B_OFF + s*1024 + ntl*64 + lane*2];
            }
            #pragma unroll
            for (int tmi = 0; tmi < 2; tmi++)
                #pragma unroll
                for (int nt = 0; nt < 8; nt++) mma16(d[tmi][nt], Afh[tmi], Bf[nt]);
            #pragma unroll
            for (int tmi = 0; tmi < 2; tmi++)
                #pragma unroll
                for (int nt = 0; nt < 8; nt++) mma16(d[tmi][nt], Afl[tmi], Bf[nt]);
            #pragma unroll
            for (int nt = 0; nt < 8; nt++) {
                int ntl = wn*8 + nt;
                *(uint2*)Bf[nt] = *(const uint2*)&sm[bw + B_OFF + 2048 + s*1024 + ntl*64 + lane*2];
            }
            #pragma unroll
            for (int tmi = 0; tmi < 2; tmi++)
                #pragma unroll
                for (int nt = 0; nt < 8; nt++) mma16(d[tmi][nt], Afh[tmi], Bf[nt]);
        }

        if (c < 7) asm volatile("cp.async.wait_group 0;" ::: "memory");
        __syncthreads();
    }

    // epilogue: rank-3 terms + constant; write fp32 + optional fp16 split image
    #pragma unroll
    for (int tmi = 0; tmi < 2; tmi++)
        #pragma unroll
        for (int nt = 0; nt < 8; nt++) {
            int rl = wm*32 + tmi*16 + r0;
            int cl = wn*64 + nt*8 + c0*2;
            int rg = rowbase + rl;
            int cg = yb*128 + cl;
            #pragma unroll
            for (int rr = 0; rr < 2; rr++) {
                int rli = rl + rr*8, rgi = rg + rr*8;
                float base0 = s_cf[6][cl]
                    + s_d[0][rli]*s_cf[0][cl] + s_d[1][rli]*s_cf[1][cl] + s_d[2][rli]*s_cf[2][cl]
                    + s_p[0][rli]*s_cf[3][cl] + s_p[1][rli]*s_cf[4][cl] + s_p[2][rli]*s_cf[5][cl];
                float base1 = s_cf[6][cl+1]
                    + s_d[0][rli]*s_cf[0][cl+1] + s_d[1][rli]*s_cf[1][cl+1] + s_d[2][rli]*s_cf[2][cl+1]
                    + s_p[0][rli]*s_cf[3][cl+1] + s_p[1][rli]*s_cf[4][cl+1] + s_p[2][rli]*s_cf[5][cl+1];
                float v0 = d[tmi][nt][rr*2+0] + base0;
                float v1 = d[tmi][nt][rr*2+1] + base1;
                *(float2*)(out + (size_t)rgi*C + cg) = make_float2(v0, v1);
                if (write_img) {
                    uint32_t h, l; split_pair(v0, v1, h, l);
                    imgH[rgi*128 + cg/2] = h;
                    imgL[rgi*128 + cg/2] = l;
                }
            }
        }
}

// ---------- host ----------
extern "C" void kernel_launch(void* const* d_in, const int* in_sizes, int n_in,
                              void* d_out, int out_size) {
    const float* xyz0 = (const float*)d_in[0];
    const int* idx0 = (const int*)d_in[1];
    const int* idx1 = (const int*)d_in[2];
    const int* idx2 = (const int*)d_in[3];
    const int* idx3 = (const int*)d_in[4];
    const int* idx4 = (const int*)d_in[5];
    const float* W_all = (const float*)d_in[6];
    const float* b_all = (const float*)d_in[7];
    const float* W4 = (const float*)d_in[8];  const float* b4 = (const float*)d_in[9];
    const float* W3 = (const float*)d_in[10]; const float* b3 = (const float*)d_in[11];
    const float* W2 = (const float*)d_in[12]; const float* b2 = (const float*)d_in[13];
    const float* W1 = (const float*)d_in[14]; const float* b1 = (const float*)d_in[15];
    const float* W0 = (const float*)d_in[16]; const float* b0 = (const float*)d_in[17];
    const float* P4 = (const float*)d_in[18]; const float* pb4 = (const float*)d_in[19];
    const float* P3 = (const float*)d_in[20]; const float* pb3 = (const float*)d_in[21];
    const float* P2 = (const float*)d_in[22]; const float* pb2 = (const float*)d_in[23];
    const float* P1 = (const float*)d_in[24]; const float* pb1 = (const float*)d_in[25];
    const float* P0 = (const float*)d_in[26]; const float* pb0 = (const float*)d_in[27];
    float* out = (float*)d_out;

    float *cls4p, *x1, *x2, *x3, *x4, *coef;
    uint32_t *bh, *bl, *H0, *L0, *H1, *L1;
    int *k34, *k23, *k12;
    cudaGetSymbolAddress((void**)&cls4p, g_cls4);
    cudaGetSymbolAddress((void**)&x1, g_xyz1);
    cudaGetSymbolAddress((void**)&x2, g_xyz2);
    cudaGetSymbolAddress((void**)&x3, g_xyz3);
    cudaGetSymbolAddress((void**)&x4, g_xyz4);
    cudaGetSymbolAddress((void**)&k34, g_k34);
    cudaGetSymbolAddress((void**)&k23, g_k23);
    cudaGetSymbolAddress((void**)&k12, g_k12);
    cudaGetSymbolAddress((void**)&bh, g_Bh16);
    cudaGetSymbolAddress((void**)&bl, g_Bl16);
    cudaGetSymbolAddress((void**)&H0, g_H0);
    cudaGetSymbolAddress((void**)&L0, g_L0);
    cudaGetSymbolAddress((void**)&H1, g_H1);
    cudaGetSymbolAddress((void**)&L1, g_L1);
    cudaGetSymbolAddress((void**)&coef, g_coef);

    cudaFuncSetAttribute(pe_mma, cudaFuncAttributeMaxDynamicSharedMemorySize, SMEMB);

    gather_kernel<<<(NL1+255)/256, 256>>>(xyz0, idx1, x1, NL1);
    gather_kernel<<<(NL2+255)/256, 256>>>(xyz0, idx2, x2, NL2);
    gather_kernel<<<(NL3+255)/256, 256>>>(xyz0, idx3, x3, NL3);
    gather_kernel<<<(NL4+255)/256, 256>>>(xyz0, idx4, x4, NL4);

    cls4_kernel<<<1, 256>>>(xyz0, W_all, b_all, cls4p);

    const float* Ps[5]  = {P4, P3, P2, P1, P0};
    const float* pbs[5] = {pb4, pb3, pb2, pb1, pb0};
    const float* Ws[5]  = {W4, W3, W2, W1, W0};
    const float* bs[5]  = {b4, b3, b2, b1, b0};
    for (int i = 0; i < 5; i++) {
        prep_B<<<128, 256>>>(Ps[i], bh + (size_t)i*32768, bl + (size_t)i*32768);
        prep_coef<<<1, 256>>>(Ws[i], bs[i], W_all, b_all, Ps[i], pbs[i],
                              cls4p, i == 0 ? 1 : 0, coef + (size_t)i*7*256);
    }

    nn_kernel<<<NL3/256, 256>>>(x3, x4, NL4, k34);
    nn_kernel<<<NL2/256, 256>>>(x2, x3, NL3, k23);
    nn_kernel<<<NL1/256, 256>>>(x1, x2, NL2, k12);

    // level 4: epilogue-only, writes pe4 + image buf0
    pe4_kernel<<<NL4, 128>>>(x4, xyz0, coef + 0, out + OFF4, H0, L0);
    // level 3: src buf0 -> img buf1
    pe_mma<<<dim3(NL3/128, 2), 256, SMEMB>>>(k34, x3, x4, xyz0, H0, L0,
        bh + 1*(size_t)32768, bl + 1*(size_t)32768, coef + 1*(size_t)7*256,
        out + OFF3, H1, L1, 1);
    // level 2: src buf1 -> img buf0
    pe_mma<<<dim3(NL2/128, 2), 256, SMEMB>>>(k23, x2, x3, xyz0, H1, L1,
        bh + 2*(size_t)32768, bl + 2*(size_t)32768, coef + 2*(size_t)7*256,
        out + OFF2, H0, L0, 1);
    // level 1: src buf0 -> img buf1
    pe_mma<<<dim3(NL1/128, 2), 256, SMEMB>>>(k12, x1, x2, xyz0, H0, L0,
        bh + 3*(size_t)32768, bl + 3*(size_t)32768, coef + 3*(size_t)7*256,
        out + OFF1, H1, L1, 1);
    // level 0: src buf1, no image
    pe_mma<<<dim3(NL0/128, 2), 256, SMEMB>>>(idx0, xyz0, x1, xyz0, H1, L1,
        bh + 4*(size_t)32768, bl + 4*(size_t)32768, coef + 4*(size_t)7*256,
        out + OFF0, H0, L0, 0);
}

// round 8
// speedup vs baseline: 1.0079x; 1.0079x over previous
#include <cuda_runtime.h>
#include <cuda_fp16.h>
#include <cstdint>

#define NL0 65536
#define NL1 16384
#define NL2 4096
#define NL3 1024
#define NL4 256
#define C   256

#define OFF4 0
#define OFF3 (NL4*C)
#define OFF2 (OFF3 + NL3*C)
#define OFF1 (OFF2 + NL2*C)
#define OFF0 (OFF1 + NL1*C)

// B pre-split (k<256 only), fragment-major: [ch8][s2][ntg32][T32][reg2]
__device__ uint32_t g_Bh16[5][32768];
__device__ uint32_t g_Bl16[5][32768];
// per-level epilogue coefficients: [lvl][ WP(3) | WallP(3) | cvec ][256]
__device__ float g_coef[5][7 * 256];
__device__ float g_cls4[C];
__device__ float g_xyz1[NL1 * 3];
__device__ float g_xyz2[NL2 * 3];
__device__ float g_xyz3[NL3 * 3];
__device__ float g_xyz4[NL4 * 3];
__device__ int   g_k34[NL3];
__device__ int   g_k23[NL2];
__device__ int   g_k12[NL1];

__device__ __forceinline__ uint32_t smem_u32(const void* p) {
    uint32_t a;
    asm("{ .reg .u64 t; cvta.to.shared.u64 t, %1; cvt.u32.u64 %0, t; }" : "=r"(a) : "l"(p));
    return a;
}
__device__ __forceinline__ void splith(float v, __half& h, __half& l) {
    h = __float2half_rn(v);
    l = __float2half_rn(v - __half2float(h));
}
__device__ __forceinline__ uint32_t packh(__half a, __half b) {
    return (uint32_t)__half_as_ushort(a) | ((uint32_t)__half_as_ushort(b) << 16);
}
__device__ __forceinline__ void split_pair(float v0, float v1, uint32_t& h, uint32_t& l) {
    __half2 hh = __float22half2_rn(make_float2(v0, v1));
    float2 bk = __half22float2(hh);
    __half2 ll = __float22half2_rn(make_float2(v0 - bk.x, v1 - bk.y));
    h = *(uint32_t*)&hh; l = *(uint32_t*)&ll;
}
__device__ __forceinline__ void mma16(float* d, const uint32_t* a, const uint32_t* b) {
    asm volatile("mma.sync.aligned.m16n8k16.row.col.f32.f16.f16.f32 "
        "{%0,%1,%2,%3}, {%4,%5,%6,%7}, {%8,%9}, {%0,%1,%2,%3};"
        : "+f"(d[0]), "+f"(d[1]), "+f"(d[2]), "+f"(d[3])
        : "r"(a[0]), "r"(a[1]), "r"(a[2]), "r"(a[3]), "r"(b[0]), "r"(b[1]));
}
#define LDM4(r, a)                                                                  \
    asm volatile("ldmatrix.sync.aligned.m8n8.x4.shared.b16 {%0,%1,%2,%3}, [%4];"    \
        : "=r"((r)[0]), "=r"((r)[1]), "=r"((r)[2]), "=r"((r)[3]) : "r"(a))

// ---------- small kernels ----------
__global__ void gather_kernel(const float* __restrict__ xyz0, const int* __restrict__ idx,
                              float* __restrict__ out, int M) {
    int i = blockIdx.x * blockDim.x + threadIdx.x;
    if (i < M) {
        int s = idx[i];
        out[i*3+0] = xyz0[s*3+0]; out[i*3+1] = xyz0[s*3+1]; out[i*3+2] = xyz0[s*3+2];
    }
}
__global__ void prep_B(const float* __restrict__ P, uint32_t* __restrict__ Bh,
                       uint32_t* __restrict__ Bl) {
    int i = blockIdx.x * 256 + threadIdx.x;           // 32768
    int reg = i & 1, T = (i >> 1) & 31, ntg = (i >> 6) & 31, s = (i >> 11) & 1, ch = i >> 12;
    int k = ch*32 + s*16 + (T & 3)*2 + reg*8;
    int n = ntg*8 + (T >> 2);
    __half h0, l0, h1, l1;
    splith(P[k*C + n], h0, l0);
    splith(P[(k+1)*C + n], h1, l1);
    Bh[i] = packh(h0, h1);
    Bl[i] = packh(l0, l1);
}
__global__ void cls4_kernel(const float* __restrict__ xyz0, const float* __restrict__ W,
                            const float* __restrict__ b, float* __restrict__ cls4) {
    int t = threadIdx.x;
    float w0 = W[t], w1 = W[C+t], w2 = W[2*C+t], bb = b[t];
    float m = -3.4e38f;
    for (int i = 0; i < NL4; i++) {
        float v = fmaf(xyz0[i*3+0], w0, fmaf(xyz0[i*3+1], w1, fmaf(xyz0[i*3+2], w2, bb)));
        m = fmaxf(m, v);
    }
    cls4[t] = m;
}
__global__ void prep_coef(const float* __restrict__ W, const float* __restrict__ b,
                          const float* __restrict__ Wall, const float* __restrict__ ball,
                          const float* __restrict__ P, const float* __restrict__ pb,
                          const float* __restrict__ cls4, int lvl4,
                          float* __restrict__ coef) {
    int n = threadIdx.x;
    float wp0=0, wp1=0, wp2=0, q0=0, q1=0, q2=0, cv=0;
    for (int c = 0; c < 256; c++) {
        float p1 = P[c*C + n], p2 = P[(256 + c)*C + n];
        wp0 = fmaf(W[c], p1, wp0);
        wp1 = fmaf(W[256 + c], p1, wp1);
        wp2 = fmaf(W[512 + c], p1, wp2);
        q0 = fmaf(Wall[c], p2, q0);
        q1 = fmaf(Wall[256 + c], p2, q1);
        q2 = fmaf(Wall[512 + c], p2, q2);
        float bc = b[c] + (lvl4 ? cls4[c] : 0.0f);
        cv = fmaf(bc, p1, fmaf(ball[c], p2, cv));
    }
    coef[0*256+n] = wp0; coef[1*256+n] = wp1; coef[2*256+n] = wp2;
    coef[3*256+n] = q0;  coef[4*256+n] = q1;  coef[5*256+n] = q2;
    coef[6*256+n] = cv + pb[n];
}
__global__ void nn_kernel(const float* __restrict__ q, const float* __restrict__ ref, int Mr,
                          int* __restrict__ out) {
    const int CH = 1024;
    __shared__ float rx[CH], ry[CH], rz[CH], rn[CH];
    int tid = blockIdx.x * blockDim.x + threadIdx.x;
    float qx = q[tid*3+0], qy = q[tid*3+1], qz = q[tid*3+2];
    float m2x = -2.f*qx, m2y = -2.f*qy, m2z = -2.f*qz;
    float best = 3.4e38f; int bi = 0;
    for (int base = 0; base < Mr; base += CH) {
        int n = min(CH, Mr - base);
        for (int j = threadIdx.x; j < n; j += blockDim.x) {
            float x = ref[(base+j)*3+0], y = ref[(base+j)*3+1], z = ref[(base+j)*3+2];
            rx[j]=x; ry[j]=y; rz[j]=z; rn[j] = x*x + y*y + z*z;
        }
        __syncthreads();
        #pragma unroll 8
        for (int j = 0; j < n; j++) {
            float d = fmaf(m2x, rx[j], fmaf(m2y, ry[j], fmaf(m2z, rz[j], rn[j])));
            if (d < best) { best = d; bi = base + j; }
        }
        __syncthreads();
    }
    out[tid] = bi;
}
// level 4: pure epilogue, no GEMM
__global__ void pe4_kernel(const float* __restrict__ xyzq, const float* __restrict__ xyz0,
                           const float* __restrict__ coef, float* __restrict__ out) {
    int r = blockIdx.x, t = threadIdx.x;
    float dx = xyzq[r*3+0], dy = xyzq[r*3+1], dz = xyzq[r*3+2];
    float x0 = xyz0[r*3+0], y0 = xyz0[r*3+1], z0 = xyz0[r*3+2];
    int c0 = 2*t, c1 = c0 + 1;
    float v0 = coef[6*256+c0] + dx*coef[c0] + dy*coef[256+c0] + dz*coef[512+c0]
             + x0*coef[3*256+c0] + y0*coef[4*256+c0] + z0*coef[5*256+c0];
    float v1 = coef[6*256+c1] + dx*coef[c1] + dy*coef[256+c1] + dz*coef[512+c1]
             + x0*coef[3*256+c1] + y0*coef[4*256+c1] + z0*coef[5*256+c1];
    *(float2*)(out + (size_t)r*C + c0) = make_float2(v0, v1);
}

// ---------- pe GEMM: D = split(pe_prev[knn]) @ P1 (3-pass) + rank-3 fp32 epilogue ----
#define AL_OFF 2560
#define B_OFF  5120
#define BUFW   9216
#define SMEMB  (2 * BUFW * 4)

__global__ void __launch_bounds__(256, 2)
pe_mma(const int* __restrict__ knn,
       const float* __restrict__ xyzq, const float* __restrict__ xyzr,
       const float* __restrict__ xyz0, const float* __restrict__ pe_prev,
       const uint32_t* __restrict__ Bh, const uint32_t* __restrict__ Bl,
       const float* __restrict__ coef, float* __restrict__ out)
{
    extern __shared__ uint32_t sm[];
    __shared__ float s_d[3][128], s_p[3][128];
    __shared__ float s_cf[7][128];

    const int t = threadIdx.x, lane = t & 31, wid = t >> 5;
    const int wm = wid & 3, wn = wid >> 2;
    const int rowbase = blockIdx.x * 128;
    const int yb = blockIdx.y;
    const uint32_t sbase = smem_u32(sm);

    const int arow = t & 127, ah2 = t >> 7;
    const int rowg = rowbase + arow;
    const float* prow;
    {
        int kk = knn[rowg];
        prow = pe_prev + (size_t)kk * C;
        if (t < 128) {
            s_d[0][t] = xyzq[rowg*3+0] - xyzr[kk*3+0];
            s_d[1][t] = xyzq[rowg*3+1] - xyzr[kk*3+1];
            s_d[2][t] = xyzq[rowg*3+2] - xyzr[kk*3+2];
            s_p[0][t] = xyz0[rowg*3+0];
            s_p[1][t] = xyz0[rowg*3+1];
            s_p[2][t] = xyz0[rowg*3+2];
        } else {
            // redundant loads keep both halves uniform; harmless
        }
    }
    {
        int j = t >> 7;
        #pragma unroll
        for (int jj = j; jj < 7; jj += 2) s_cf[jj][t & 127] = coef[jj*256 + yb*128 + (t & 127)];
    }
    __syncthreads();

    #define COPY_B(c) do {                                                             \
        const int bw_ = ((c) & 1) * BUFW;                                              \
        const uint32_t* s0_ = Bh + (size_t)(c)*4096 + yb*1024 + t*4;                   \
        const uint32_t* s1_ = Bl + (size_t)(c)*4096 + yb*1024 + t*4;                   \
        _Pragma("unroll")                                                              \
        for (int s_ = 0; s_ < 2; s_++) {                                               \
            asm volatile("cp.async.cg.shared.global [%0], [%1], 16;"                   \
                :: "r"(sbase + 4*(bw_ + B_OFF + s_*1024 + t*4)),                       \
                   "l"(s0_ + s_*2048) : "memory");                                     \
            asm volatile("cp.async.cg.shared.global [%0], [%1], 16;"                   \
                :: "r"(sbase + 4*(bw_ + B_OFF + 2048 + s_*1024 + t*4)),                \
                   "l"(s1_ + s_*2048) : "memory");                                     \
        }                                                                              \
    } while (0)

    // A fill: gather 16 fp32 from pe_prev row, split, STS (round-6 proven path)
    #define FILL_A(c) do {                                                             \
        const int bw_ = ((c) & 1) * BUFW;                                              \
        int kg_ = (c)*32 + ah2*16;                                                     \
        float4 v0_ = *(const float4*)(prow + kg_);                                     \
        float4 v1_ = *(const float4*)(prow + kg_ + 4);                                 \
        float4 v2_ = *(const float4*)(prow + kg_ + 8);                                 \
        float4 v3_ = *(const float4*)(prow + kg_ + 12);                                \
        uint32_t hw_[8], lw_[8];                                                       \
        split_pair(v0_.x, v0_.y, hw_[0], lw_[0]);                                      \
        split_pair(v0_.z, v0_.w, hw_[1], lw_[1]);                                      \
        split_pair(v1_.x, v1_.y, hw_[2], lw_[2]);                                      \
        split_pair(v1_.z, v1_.w, hw_[3], lw_[3]);                                      \
        split_pair(v2_.x, v2_.y, hw_[4], lw_[4]);                                      \
        split_pair(v2_.z, v2_.w, hw_[5], lw_[5]);                                      \
        split_pair(v3_.x, v3_.y, hw_[6], lw_[6]);                                      \
        split_pair(v3_.z, v3_.w, hw_[7], lw_[7]);                                      \
        uint4* dh_ = (uint4*)&sm[bw_ + arow*20 + ah2*8];                               \
        dh_[0] = *(uint4*)&hw_[0]; dh_[1] = *(uint4*)&hw_[4];                          \
        uint4* dl_ = (uint4*)&sm[bw_ + AL_OFF + arow*20 + ah2*8];                      \
        dl_[0] = *(uint4*)&lw_[0]; dl_[1] = *(uint4*)&lw_[4];                          \
    } while (0)

    float d[2][8][4];
    #pragma unroll
    for (int i = 0; i < 2; i++)
        #pragma unroll
        for (int j = 0; j < 8; j++)
            #pragma unroll
            for (int q = 0; q < 4; q++) d[i][j][q] = 0.0f;

    COPY_B(0);
    FILL_A(0);
    asm volatile("cp.async.commit_group;" ::: "memory");
    asm volatile("cp.async.wait_group 0;" ::: "memory");
    __syncthreads();

    const int r0 = lane >> 2, c0 = lane & 3;
    const int lr = (lane & 7) + ((lane >> 3) & 1) * 8;
    const int kseg = (lane >> 4) * 4;

    for (int c = 0; c < 8; c++) {
        if (c < 7) {
            COPY_B(c + 1);
            FILL_A(c + 1);
            asm volatile("cp.async.commit_group;" ::: "memory");
        }

        const int bw = (c & 1) * BUFW;
        #pragma unroll
        for (int s = 0; s < 2; s++) {
            uint32_t Afh[2][4], Afl[2][4];
            #pragma unroll
            for (int tmi = 0; tmi < 2; tmi++) {
                uint32_t aw = sbase + 4*(bw + (wm*32 + tmi*16 + lr)*20 + s*8 + kseg);
                LDM4(Afh[tmi], aw);
                LDM4(Afl[tmi], aw + AL_OFF*4);
            }
            uint32_t Bf[8][2];
            #pragma unroll
            for (int nt = 0; nt < 8; nt++) {
                int ntl = wn*8 + nt;
                *(uint2*)Bf[nt] = *(const uint2*)&sm[bw + B_OFF + s*1024 + ntl*64 + lane*2];
            }
            #pragma unroll
            for (int tmi = 0; tmi < 2; tmi++)
                #pragma unroll
                for (int nt = 0; nt < 8; nt++) mma16(d[tmi][nt], Afh[tmi], Bf[nt]);
            #pragma unroll
            for (int tmi = 0; tmi < 2; tmi++)
                #pragma unroll
                for (int nt = 0; nt < 8; nt++) mma16(d[tmi][nt], Afl[tmi], Bf[nt]);
            #pragma unroll
            for (int nt = 0; nt < 8; nt++) {
                int ntl = wn*8 + nt;
                *(uint2*)Bf[nt] = *(const uint2*)&sm[bw + B_OFF + 2048 + s*1024 + ntl*64 + lane*2];
            }
            #pragma unroll
            for (int tmi = 0; tmi < 2; tmi++)
                #pragma unroll
                for (int nt = 0; nt < 8; nt++) mma16(d[tmi][nt], Afh[tmi], Bf[nt]);
        }

        if (c < 7) asm volatile("cp.async.wait_group 0;" ::: "memory");
        __syncthreads();
    }

    // epilogue: rank-3 terms + constant, fp32 exact
    #pragma unroll
    for (int tmi = 0; tmi < 2; tmi++)
        #pragma unroll
        for (int nt = 0; nt < 8; nt++) {
            int rl = wm*32 + tmi*16 + r0;
            int cl = wn*64 + nt*8 + c0*2;
            int rg = rowbase + rl;
            int cg = yb*128 + cl;
            #pragma unroll
            for (int rr = 0; rr < 2; rr++) {
                int rli = rl + rr*8, rgi = rg + rr*8;
                float base0 = s_cf[6][cl]
                    + s_d[0][rli]*s_cf[0][cl] + s_d[1][rli]*s_cf[1][cl] + s_d[2][rli]*s_cf[2][cl]
                    + s_p[0][rli]*s_cf[3][cl] + s_p[1][rli]*s_cf[4][cl] + s_p[2][rli]*s_cf[5][cl];
                float base1 = s_cf[6][cl+1]
                    + s_d[0][rli]*s_cf[0][cl+1] + s_d[1][rli]*s_cf[1][cl+1] + s_d[2][rli]*s_cf[2][cl+1]
                    + s_p[0][rli]*s_cf[3][cl+1] + s_p[1][rli]*s_cf[4][cl+1] + s_p[2][rli]*s_cf[5][cl+1];
                *(float2*)(out + (size_t)rgi*C + cg) =
                    make_float2(d[tmi][nt][rr*2+0] + base0, d[tmi][nt][rr*2+1] + base1);
            }
        }
}

// ---------- host ----------
extern "C" void kernel_launch(void* const* d_in, const int* in_sizes, int n_in,
                              void* d_out, int out_size) {
    const float* xyz0 = (const float*)d_in[0];
    const int* idx0 = (const int*)d_in[1];
    const int* idx1 = (const int*)d_in[2];
    const int* idx2 = (const int*)d_in[3];
    const int* idx3 = (const int*)d_in[4];
    const int* idx4 = (const int*)d_in[5];
    const float* W_all = (const float*)d_in[6];
    const float* b_all = (const float*)d_in[7];
    const float* W4 = (const float*)d_in[8];  const float* b4 = (const float*)d_in[9];
    const float* W3 = (const float*)d_in[10]; const float* b3 = (const float*)d_in[11];
    const float* W2 = (const float*)d_in[12]; const float* b2 = (const float*)d_in[13];
    const float* W1 = (const float*)d_in[14]; const float* b1 = (const float*)d_in[15];
    const float* W0 = (const float*)d_in[16]; const float* b0 = (const float*)d_in[17];
    const float* P4 = (const float*)d_in[18]; const float* pb4 = (const float*)d_in[19];
    const float* P3 = (const float*)d_in[20]; const float* pb3 = (const float*)d_in[21];
    const float* P2 = (const float*)d_in[22]; const float* pb2 = (const float*)d_in[23];
    const float* P1 = (const float*)d_in[24]; const float* pb1 = (const float*)d_in[25];
    const float* P0 = (const float*)d_in[26]; const float* pb0 = (const float*)d_in[27];
    float* out = (float*)d_out;

    float *cls4p, *x1, *x2, *x3, *x4, *coef;
    uint32_t *bh, *bl;
    int *k34, *k23, *k12;
    cudaGetSymbolAddress((void**)&cls4p, g_cls4);
    cudaGetSymbolAddress((void**)&x1, g_xyz1);
    cudaGetSymbolAddress((void**)&x2, g_xyz2);
    cudaGetSymbolAddress((void**)&x3, g_xyz3);
    cudaGetSymbolAddress((void**)&x4, g_xyz4);
    cudaGetSymbolAddress((void**)&k34, g_k34);
    cudaGetSymbolAddress((void**)&k23, g_k23);
    cudaGetSymbolAddress((void**)&k12, g_k12);
    cudaGetSymbolAddress((void**)&bh, g_Bh16);
    cudaGetSymbolAddress((void**)&bl, g_Bl16);
    cudaGetSymbolAddress((void**)&coef, g_coef);

    cudaFuncSetAttribute(pe_mma, cudaFuncAttributeMaxDynamicSharedMemorySize, SMEMB);

    gather_kernel<<<(NL1+255)/256, 256>>>(xyz0, idx1, x1, NL1);
    gather_kernel<<<(NL2+255)/256, 256>>>(xyz0, idx2, x2, NL2);
    gather_kernel<<<(NL3+255)/256, 256>>>(xyz0, idx3, x3, NL3);
    gather_kernel<<<(NL4+255)/256, 256>>>(xyz0, idx4, x4, NL4);

    cls4_kernel<<<1, 256>>>(xyz0, W_all, b_all, cls4p);

    const float* Ps[5]  = {P4, P3, P2, P1, P0};
    const float* pbs[5] = {pb4, pb3, pb2, pb1, pb0};
    const float* Ws[5]  = {W4, W3, W2, W1, W0};
    const float* bs[5]  = {b4, b3, b2, b1, b0};
    for (int i = 0; i < 5; i++) {
        prep_B<<<128, 256>>>(Ps[i], bh + (size_t)i*32768, bl + (size_t)i*32768);
        prep_coef<<<1, 256>>>(Ws[i], bs[i], W_all, b_all, Ps[i], pbs[i],
                              cls4p, i == 0 ? 1 : 0, coef + (size_t)i*7*256);
    }

    nn_kernel<<<NL3/256, 256>>>(x3, x4, NL4, k34);
    nn_kernel<<<NL2/256, 256>>>(x2, x3, NL3, k23);
    nn_kernel<<<NL1/256, 256>>>(x1, x2, NL2, k12);

    pe4_kernel<<<NL4, 128>>>(x4, xyz0, coef + 0, out + OFF4);
    pe_mma<<<dim3(NL3/128, 2), 256, SMEMB>>>(k34, x3, x4, xyz0, out + OFF4,
        bh + 1*(size_t)32768, bl + 1*(size_t)32768, coef + 1*(size_t)7*256, out + OFF3);
    pe_mma<<<dim3(NL2/128, 2), 256, SMEMB>>>(k23, x2, x3, xyz0, out + OFF3,
        bh + 2*(size_t)32768, bl + 2*(size_t)32768, coef + 2*(size_t)7*256, out + OFF2);
    pe_mma<<<dim3(NL1/128, 2), 256, SMEMB>>>(k12, x1, x2, xyz0, out + OFF2,
        bh + 3*(size_t)32768, bl + 3*(size_t)32768, coef + 3*(size_t)7*256, out + OFF1);
    pe_mma<<<dim3(NL0/128, 2), 256, SMEMB>>>(idx0, xyz0, x1, xyz0, out + OFF1,
        bh + 4*(size_t)32768, bl + 4*(size_t)32768, coef + 4*(size_t)7*256, out + OFF0);
}

// round 9
// speedup vs baseline: 2.3121x; 2.2939x over previous
#include <cuda_runtime.h>
#include <cuda_fp16.h>
#include <cstdint>

#define NL0 65536
#define NL1 16384
#define NL2 4096
#define NL3 1024
#define NL4 256
#define C   256

#define OFF4 0
#define OFF3 (NL4*C)
#define OFF2 (OFF3 + NL3*C)
#define OFF1 (OFF2 + NL2*C)
#define OFF0 (OFF1 + NL1*C)

// B pre-split (k<256), fragment-major: [ch8][s2][ntg32][T32][reg2]
__device__ uint32_t g_Bh16[5][32768];
__device__ uint32_t g_Bl16[5][32768];
// per-level epilogue coefficients: [lvl][ WP(3) | WallP(3) | cvec ][256]
__device__ float g_coef[5][7 * 256];
__device__ float g_cls4[C];
__device__ float g_xyz1[NL1 * 3];
__device__ float g_xyz2[NL2 * 3];
__device__ float g_xyz3[NL3 * 3];
__device__ float g_xyz4[NL4 * 3];
__device__ int   g_k34[NL3];
__device__ int   g_k23[NL2];
__device__ int   g_k12[NL1];

__device__ __forceinline__ uint32_t smem_u32(const void* p) {
    uint32_t a;
    asm("{ .reg .u64 t; cvta.to.shared.u64 t, %1; cvt.u32.u64 %0, t; }" : "=r"(a) : "l"(p));
    return a;
}
__device__ __forceinline__ void splith(float v, __half& h, __half& l) {
    h = __float2half_rn(v);
    l = __float2half_rn(v - __half2float(h));
}
__device__ __forceinline__ uint32_t packh(__half a, __half b) {
    return (uint32_t)__half_as_ushort(a) | ((uint32_t)__half_as_ushort(b) << 16);
}
__device__ __forceinline__ void split_pair(float v0, float v1, uint32_t& h, uint32_t& l) {
    __half2 hh = __float22half2_rn(make_float2(v0, v1));
    float2 bk = __half22float2(hh);
    __half2 ll = __float22half2_rn(make_float2(v0 - bk.x, v1 - bk.y));
    h = *(uint32_t*)&hh; l = *(uint32_t*)&ll;
}
__device__ __forceinline__ void mma16(float* d, const uint32_t* a, const uint32_t* b) {
    asm volatile("mma.sync.aligned.m16n8k16.row.col.f32.f16.f16.f32 "
        "{%0,%1,%2,%3}, {%4,%5,%6,%7}, {%8,%9}, {%0,%1,%2,%3};"
        : "+f"(d[0]), "+f"(d[1]), "+f"(d[2]), "+f"(d[3])
        : "r"(a[0]), "r"(a[1]), "r"(a[2]), "r"(a[3]), "r"(b[0]), "r"(b[1]));
}
#define LDM4(r, a)                                                                  \
    asm volatile("ldmatrix.sync.aligned.m8n8.x4.shared.b16 {%0,%1,%2,%3}, [%4];"    \
        : "=r"((r)[0]), "=r"((r)[1]), "=r"((r)[2]), "=r"((r)[3]) : "r"(a))

// ---------- small kernels ----------
__global__ void gather_kernel(const float* __restrict__ xyz0, const int* __restrict__ idx,
                              float* __restrict__ out, int M) {
    int i = blockIdx.x * blockDim.x + threadIdx.x;
    if (i < M) {
        int s = idx[i];
        out[i*3+0] = xyz0[s*3+0]; out[i*3+1] = xyz0[s*3+1]; out[i*3+2] = xyz0[s*3+2];
    }
}
__global__ void prep_B(const float* __restrict__ P, uint32_t* __restrict__ Bh,
                       uint32_t* __restrict__ Bl) {
    int i = blockIdx.x * 256 + threadIdx.x;           // 32768
    int reg = i & 1, T = (i >> 1) & 31, ntg = (i >> 6) & 31, s = (i >> 11) & 1, ch = i >> 12;
    int k = ch*32 + s*16 + (T & 3)*2 + reg*8;
    int n = ntg*8 + (T >> 2);
    __half h0, l0, h1, l1;
    splith(P[k*C + n], h0, l0);
    splith(P[(k+1)*C + n], h1, l1);
    Bh[i] = packh(h0, h1);
    Bl[i] = packh(l0, l1);
}
__global__ void cls4_kernel(const float* __restrict__ xyz0, const float* __restrict__ W,
                            const float* __restrict__ b, float* __restrict__ cls4) {
    int t = threadIdx.x;
    float w0 = W[t], w1 = W[C+t], w2 = W[2*C+t], bb = b[t];
    float m = -3.4e38f;
    for (int i = 0; i < NL4; i++) {
        float v = fmaf(xyz0[i*3+0], w0, fmaf(xyz0[i*3+1], w1, fmaf(xyz0[i*3+2], w2, bb)));
        m = fmaxf(m, v);
    }
    cls4[t] = m;
}
// parallel coef: grid 8, block 256; block covers 32 n-columns, 8 k-slices
__global__ void prep_coef(const float* __restrict__ W, const float* __restrict__ b,
                          const float* __restrict__ Wall, const float* __restrict__ ball,
                          const float* __restrict__ P, const float* __restrict__ pb,
                          const float* __restrict__ cls4, int lvl4,
                          float* __restrict__ coef) {
    __shared__ float red[8][7][32];
    int t = threadIdx.x;
    int nl = t & 31, sl = t >> 5;
    int n = blockIdx.x * 32 + nl;
    float a0=0,a1=0,a2=0,a3=0,a4=0,a5=0,a6=0;
    for (int c = sl*32; c < sl*32 + 32; c++) {
        float p1 = P[c*C + n], p2 = P[(256 + c)*C + n];
        a0 = fmaf(W[c], p1, a0);
        a1 = fmaf(W[256 + c], p1, a1);
        a2 = fmaf(W[512 + c], p1, a2);
        a3 = fmaf(Wall[c], p2, a3);
        a4 = fmaf(Wall[256 + c], p2, a4);
        a5 = fmaf(Wall[512 + c], p2, a5);
        float bc = b[c] + (lvl4 ? cls4[c] : 0.0f);
        a6 = fmaf(bc, p1, fmaf(ball[c], p2, a6));
    }
    red[sl][0][nl]=a0; red[sl][1][nl]=a1; red[sl][2][nl]=a2; red[sl][3][nl]=a3;
    red[sl][4][nl]=a4; red[sl][5][nl]=a5; red[sl][6][nl]=a6;
    __syncthreads();
    if (t < 224) {
        int o = t >> 5, nn = t & 31;
        float s = 0;
        #pragma unroll
        for (int q = 0; q < 8; q++) s += red[q][o][nn];
        if (o == 6) s += pb[blockIdx.x*32 + nn];
        coef[o*256 + blockIdx.x*32 + nn] = s;
    }
}
__global__ void nn_kernel(const float* __restrict__ q, const float* __restrict__ ref, int Mr,
                          int* __restrict__ out) {
    const int CH = 1024;
    __shared__ float rx[CH], ry[CH], rz[CH], rn[CH];
    int tid = blockIdx.x * blockDim.x + threadIdx.x;
    float qx = q[tid*3+0], qy = q[tid*3+1], qz = q[tid*3+2];
    float m2x = -2.f*qx, m2y = -2.f*qy, m2z = -2.f*qz;
    float best = 3.4e38f; int bi = 0;
    for (int base = 0; base < Mr; base += CH) {
        int n = min(CH, Mr - base);
        for (int j = threadIdx.x; j < n; j += blockDim.x) {
            float x = ref[(base+j)*3+0], y = ref[(base+j)*3+1], z = ref[(base+j)*3+2];
            rx[j]=x; ry[j]=y; rz[j]=z; rn[j] = x*x + y*y + z*z;
        }
        __syncthreads();
        #pragma unroll 8
        for (int j = 0; j < n; j++) {
            float d = fmaf(m2x, rx[j], fmaf(m2y, ry[j], fmaf(m2z, rz[j], rn[j])));
            if (d < best) { best = d; bi = base + j; }
        }
        __syncthreads();
    }
    out[tid] = bi;
}
// level 4: pure epilogue, no GEMM
__global__ void pe4_kernel(const float* __restrict__ xyzq, const float* __restrict__ xyz0,
                           const float* __restrict__ coef, float* __restrict__ out) {
    int r = blockIdx.x, t = threadIdx.x;
    float dx = xyzq[r*3+0], dy = xyzq[r*3+1], dz = xyzq[r*3+2];
    float x0 = xyz0[r*3+0], y0 = xyz0[r*3+1], z0 = xyz0[r*3+2];
    int c0 = 2*t, c1 = c0 + 1;
    float v0 = coef[6*256+c0] + dx*coef[c0] + dy*coef[256+c0] + dz*coef[512+c0]
             + x0*coef[3*256+c0] + y0*coef[4*256+c0] + z0*coef[5*256+c0];
    float v1 = coef[6*256+c1] + dx*coef[c1] + dy*coef[256+c1] + dz*coef[512+c1]
             + x0*coef[3*256+c1] + y0*coef[4*256+c1] + z0*coef[5*256+c1];
    *(float2*)(out + (size_t)r*C + c0) = make_float2(v0, v1);
}

// ---------- pe GEMM: D = split(pe_prev[knn]) @ P1 (3-pass) + rank-3 fp32 epilogue ----
#define AL_OFF 2560
#define B_OFF  5120
#define BUFW   9216
#define SMEMB  (2 * BUFW * 4)

__global__ void __launch_bounds__(256, 2)
pe_mma(const int* __restrict__ knn,
       const float* __restrict__ xyzq, const float* __restrict__ xyzr,
       const float* __restrict__ xyz0, const float* __restrict__ pe_prev,
       const uint32_t* __restrict__ Bh, const uint32_t* __restrict__ Bl,
       const float* __restrict__ coef, float* __restrict__ out)
{
    extern __shared__ uint32_t sm[];
    const int t = threadIdx.x, lane = t & 31, wid = t >> 5;
    const int wm = wid & 3, wn = wid >> 2;
    const int rowbase = blockIdx.x * 128;
    const int yb = blockIdx.y;
    const uint32_t sbase = smem_u32(sm);

    const int arow = t & 127, ah2 = t >> 7;
    const int rowg = rowbase + arow;
    const float* prow = pe_prev + (size_t)knn[rowg] * C;

    #define COPY_B(c) do {                                                             \
        const int bw_ = ((c) & 1) * BUFW;                                              \
        const uint32_t* s0_ = Bh + (size_t)(c)*4096 + yb*1024 + t*4;                   \
        const uint32_t* s1_ = Bl + (size_t)(c)*4096 + yb*1024 + t*4;                   \
        _Pragma("unroll")                                                              \
        for (int s_ = 0; s_ < 2; s_++) {                                               \
            asm volatile("cp.async.cg.shared.global [%0], [%1], 16;"                   \
                :: "r"(sbase + 4*(bw_ + B_OFF + s_*1024 + t*4)),                       \
                   "l"(s0_ + s_*2048) : "memory");                                     \
            asm volatile("cp.async.cg.shared.global [%0], [%1], 16;"                   \
                :: "r"(sbase + 4*(bw_ + B_OFF + 2048 + s_*1024 + t*4)),                \
                   "l"(s1_ + s_*2048) : "memory");                                     \
        }                                                                              \
    } while (0)

    #define FILL_A(c) do {                                                             \
        const int bw_ = ((c) & 1) * BUFW;                                              \
        int kg_ = (c)*32 + ah2*16;                                                     \
        float4 v0_ = *(const float4*)(prow + kg_);                                     \
        float4 v1_ = *(const float4*)(prow + kg_ + 4);                                 \
        float4 v2_ = *(const float4*)(prow + kg_ + 8);                                 \
        float4 v3_ = *(const float4*)(prow + kg_ + 12);                                \
        uint32_t hw_[8], lw_[8];                                                       \
        split_pair(v0_.x, v0_.y, hw_[0], lw_[0]);                                      \
        split_pair(v0_.z, v0_.w, hw_[1], lw_[1]);                                      \
        split_pair(v1_.x, v1_.y, hw_[2], lw_[2]);                                      \
        split_pair(v1_.z, v1_.w, hw_[3], lw_[3]);                                      \
        split_pair(v2_.x, v2_.y, hw_[4], lw_[4]);                                      \
        split_pair(v2_.z, v2_.w, hw_[5], lw_[5]);                                      \
        split_pair(v3_.x, v3_.y, hw_[6], lw_[6]);                                      \
        split_pair(v3_.z, v3_.w, hw_[7], lw_[7]);                                      \
        uint4* dh_ = (uint4*)&sm[bw_ + arow*20 + ah2*8];                               \
        dh_[0] = *(uint4*)&hw_[0]; dh_[1] = *(uint4*)&hw_[4];                          \
        uint4* dl_ = (uint4*)&sm[bw_ + AL_OFF + arow*20 + ah2*8];                      \
        dl_[0] = *(uint4*)&lw_[0]; dl_[1] = *(uint4*)&lw_[4];                          \
    } while (0)

    float d[2][8][4];
    #pragma unroll
    for (int i = 0; i < 2; i++)
        #pragma unroll
        for (int j = 0; j < 8; j++)
            #pragma unroll
            for (int q = 0; q < 4; q++) d[i][j][q] = 0.0f;

    COPY_B(0);
    FILL_A(0);
    asm volatile("cp.async.commit_group;" ::: "memory");
    asm volatile("cp.async.wait_group 0;" ::: "memory");
    __syncthreads();

    const int r0 = lane >> 2, c0 = lane & 3;
    const int lr = (lane & 7) + ((lane >> 3) & 1) * 8;
    const int kseg = (lane >> 4) * 4;

    for (int c = 0; c < 8; c++) {
        if (c < 7) {
            COPY_B(c + 1);
            FILL_A(c + 1);
            asm volatile("cp.async.commit_group;" ::: "memory");
        }

        const int bw = (c & 1) * BUFW;
        #pragma unroll
        for (int s = 0; s < 2; s++) {
            uint32_t Afh[2][4], Afl[2][4];
            #pragma unroll
            for (int tmi = 0; tmi < 2; tmi++) {
                uint32_t aw = sbase + 4*(bw + (wm*32 + tmi*16 + lr)*20 + s*8 + kseg);
                LDM4(Afh[tmi], aw);
                LDM4(Afl[tmi], aw + AL_OFF*4);
            }
            uint32_t Bf[8][2];
            #pragma unroll
            for (int nt = 0; nt < 8; nt++) {
                int ntl = wn*8 + nt;
                *(uint2*)Bf[nt] = *(const uint2*)&sm[bw + B_OFF + s*1024 + ntl*64 + lane*2];
            }
            #pragma unroll
            for (int tmi = 0; tmi < 2; tmi++)
                #pragma unroll
                for (int nt = 0; nt < 8; nt++) mma16(d[tmi][nt], Afh[tmi], Bf[nt]);
            #pragma unroll
            for (int tmi = 0; tmi < 2; tmi++)
                #pragma unroll
                for (int nt = 0; nt < 8; nt++) mma16(d[tmi][nt], Afl[tmi], Bf[nt]);
            #pragma unroll
            for (int nt = 0; nt < 8; nt++) {
                int ntl = wn*8 + nt;
                *(uint2*)Bf[nt] = *(const uint2*)&sm[bw + B_OFF + 2048 + s*1024 + ntl*64 + lane*2];
            }
            #pragma unroll
            for (int tmi = 0; tmi < 2; tmi++)
                #pragma unroll
                for (int nt = 0; nt < 8; nt++) mma16(d[tmi][nt], Afh[tmi], Bf[nt]);
        }

        if (c < 7) asm volatile("cp.async.wait_group 0;" ::: "memory");
        __syncthreads();
    }

    // ---- self-contained epilogue: refill buffer-0 smem with coefs + row data ----
    float* cfs = (float*)sm;            // [7][128]
    float* dps = (float*)(sm + 896);    // [6][128]
    if (t < 128) {
        int kk = knn[rowg];
        dps[0*128 + t] = xyzq[rowg*3+0] - xyzr[kk*3+0];
        dps[1*128 + t] = xyzq[rowg*3+1] - xyzr[kk*3+1];
        dps[2*128 + t] = xyzq[rowg*3+2] - xyzr[kk*3+2];
        dps[3*128 + t] = xyz0[rowg*3+0];
        dps[4*128 + t] = xyz0[rowg*3+1];
        dps[5*128 + t] = xyz0[rowg*3+2];
    } else {
        int u = t - 128;
        #pragma unroll
        for (int jj = 0; jj < 7; jj++) cfs[jj*128 + u] = coef[jj*256 + yb*128 + u];
    }
    __syncthreads();

    #pragma unroll
    for (int tmi = 0; tmi < 2; tmi++)
        #pragma unroll
        for (int nt = 0; nt < 8; nt++) {
            int rl = wm*32 + tmi*16 + r0;
            int cl = wn*64 + nt*8 + c0*2;
            int rg = rowbase + rl;
            int cg = yb*128 + cl;
            #pragma unroll
            for (int rr = 0; rr < 2; rr++) {
                int rli = rl + rr*8, rgi = rg + rr*8;
                float base0 = cfs[6*128+cl]
                    + dps[0*128+rli]*cfs[0*128+cl] + dps[1*128+rli]*cfs[1*128+cl]
                    + dps[2*128+rli]*cfs[2*128+cl] + dps[3*128+rli]*cfs[3*128+cl]
                    + dps[4*128+rli]*cfs[4*128+cl] + dps[5*128+rli]*cfs[5*128+cl];
                float base1 = cfs[6*128+cl+1]
                    + dps[0*128+rli]*cfs[0*128+cl+1] + dps[1*128+rli]*cfs[1*128+cl+1]
                    + dps[2*128+rli]*cfs[2*128+cl+1] + dps[3*128+rli]*cfs[3*128+cl+1]
                    + dps[4*128+rli]*cfs[4*128+cl+1] + dps[5*128+rli]*cfs[5*128+cl+1];
                *(float2*)(out + (size_t)rgi*C + cg) =
                    make_float2(d[tmi][nt][rr*2+0] + base0, d[tmi][nt][rr*2+1] + base1);
            }
        }
}

// ---------- host ----------
extern "C" void kernel_launch(void* const* d_in, const int* in_sizes, int n_in,
                              void* d_out, int out_size) {
    const float* xyz0 = (const float*)d_in[0];
    const int* idx0 = (const int*)d_in[1];
    const int* idx1 = (const int*)d_in[2];
    const int* idx2 = (const int*)d_in[3];
    const int* idx3 = (const int*)d_in[4];
    const int* idx4 = (const int*)d_in[5];
    const float* W_all = (const float*)d_in[6];
    const float* b_all = (const float*)d_in[7];
    const float* W4 = (const float*)d_in[8];  const float* b4 = (const float*)d_in[9];
    const float* W3 = (const float*)d_in[10]; const float* b3 = (const float*)d_in[11];
    const float* W2 = (const float*)d_in[12]; const float* b2 = (const float*)d_in[13];
    const float* W1 = (const float*)d_in[14]; const float* b1 = (const float*)d_in[15];
    const float* W0 = (const float*)d_in[16]; const float* b0 = (const float*)d_in[17];
    const float* P4 = (const float*)d_in[18]; const float* pb4 = (const float*)d_in[19];
    const float* P3 = (const float*)d_in[20]; const float* pb3 = (const float*)d_in[21];
    const float* P2 = (const float*)d_in[22]; const float* pb2 = (const float*)d_in[23];
    const float* P1 = (const float*)d_in[24]; const float* pb1 = (const float*)d_in[25];
    const float* P0 = (const float*)d_in[26]; const float* pb0 = (const float*)d_in[27];
    float* out = (float*)d_out;

    float *cls4p, *x1, *x2, *x3, *x4, *coef;
    uint32_t *bh, *bl;
    int *k34, *k23, *k12;
    cudaGetSymbolAddress((void**)&cls4p, g_cls4);
    cudaGetSymbolAddress((void**)&x1, g_xyz1);
    cudaGetSymbolAddress((void**)&x2, g_xyz2);
    cudaGetSymbolAddress((void**)&x3, g_xyz3);
    cudaGetSymbolAddress((void**)&x4, g_xyz4);
    cudaGetSymbolAddress((void**)&k34, g_k34);
    cudaGetSymbolAddress((void**)&k23, g_k23);
    cudaGetSymbolAddress((void**)&k12, g_k12);
    cudaGetSymbolAddress((void**)&bh, g_Bh16);
    cudaGetSymbolAddress((void**)&bl, g_Bl16);
    cudaGetSymbolAddress((void**)&coef, g_coef);

    cudaFuncSetAttribute(pe_mma, cudaFuncAttributeMaxDynamicSharedMemorySize, SMEMB);

    gather_kernel<<<(NL1+255)/256, 256>>>(xyz0, idx1, x1, NL1);
    gather_kernel<<<(NL2+255)/256, 256>>>(xyz0, idx2, x2, NL2);
    gather_kernel<<<(NL3+255)/256, 256>>>(xyz0, idx3, x3, NL3);
    gather_kernel<<<(NL4+255)/256, 256>>>(xyz0, idx4, x4, NL4);

    cls4_kernel<<<1, 256>>>(xyz0, W_all, b_all, cls4p);

    const float* Ps[5]  = {P4, P3, P2, P1, P0};
    const float* pbs[5] = {pb4, pb3, pb2, pb1, pb0};
    const float* Ws[5]  = {W4, W3, W2, W1, W0};
    const float* bs[5]  = {b4, b3, b2, b1, b0};
    for (int i = 0; i < 5; i++) {
        prep_B<<<128, 256>>>(Ps[i], bh + (size_t)i*32768, bl + (size_t)i*32768);
        prep_coef<<<8, 256>>>(Ws[i], bs[i], W_all, b_all, Ps[i], pbs[i],
                              cls4p, i == 0 ? 1 : 0, coef + (size_t)i*7*256);
    }

    nn_kernel<<<NL3/256, 256>>>(x3, x4, NL4, k34);
    nn_kernel<<<NL2/256, 256>>>(x2, x3, NL3, k23);
    nn_kernel<<<NL1/256, 256>>>(x1, x2, NL2, k12);

    pe4_kernel<<<NL4, 128>>>(x4, xyz0, coef + 0, out + OFF4);
    pe_mma<<<dim3(NL3/128, 2), 256, SMEMB>>>(k34, x3, x4, xyz0, out + OFF4,
        bh + 1*(size_t)32768, bl + 1*(size_t)32768, coef + 1*(size_t)7*256, out + OFF3);
    pe_mma<<<dim3(NL2/128, 2), 256, SMEMB>>>(k23, x2, x3, xyz0, out + OFF3,
        bh + 2*(size_t)32768, bl + 2*(size_t)32768, coef + 2*(size_t)7*256, out + OFF2);
    pe_mma<<<dim3(NL1/128, 2), 256, SMEMB>>>(k12, x1, x2, xyz0, out + OFF2,
        bh + 3*(size_t)32768, bl + 3*(size_t)32768, coef + 3*(size_t)7*256, out + OFF1);
    pe_mma<<<dim3(NL0/128, 2), 256, SMEMB>>>(idx0, xyz0, x1, xyz0, out + OFF1,
        bh + 4*(size_t)32768, bl + 4*(size_t)32768, coef + 4*(size_t)7*256, out + OFF0);
}

// round 10
// speedup vs baseline: 3.3305x; 1.4404x over previous
#include <cuda_runtime.h>
#include <cuda_fp16.h>
#include <cstdint>

#define NL0 65536
#define NL1 16384
#define NL2 4096
#define NL3 1024
#define NL4 256
#define C   256

#define OFF4 0
#define OFF3 (NL4*C)
#define OFF2 (OFF3 + NL3*C)
#define OFF1 (OFF2 + NL2*C)
#define OFF0 (OFF1 + NL1*C)

__device__ uint32_t g_Bh16[5][32768];
__device__ uint32_t g_Bl16[5][32768];
__device__ float g_coef[5][7 * 256];
__device__ float g_cls4[C];
__device__ float g_xyz1[NL1 * 3];
__device__ float g_xyz2[NL2 * 3];
__device__ float g_xyz3[NL3 * 3];
__device__ float g_xyz4[NL4 * 3];
__device__ int   g_k34[NL3];
__device__ int   g_k23[NL2];
__device__ int   g_k12[NL1];

__device__ __forceinline__ uint32_t smem_u32(const void* p) {
    uint32_t a;
    asm("{ .reg .u64 t; cvta.to.shared.u64 t, %1; cvt.u32.u64 %0, t; }" : "=r"(a) : "l"(p));
    return a;
}
__device__ __forceinline__ void splith(float v, __half& h, __half& l) {
    h = __float2half_rn(v);
    l = __float2half_rn(v - __half2float(h));
}
__device__ __forceinline__ uint32_t packh(__half a, __half b) {
    return (uint32_t)__half_as_ushort(a) | ((uint32_t)__half_as_ushort(b) << 16);
}
__device__ __forceinline__ void split_pair(float v0, float v1, uint32_t& h, uint32_t& l) {
    __half2 hh = __float22half2_rn(make_float2(v0, v1));
    float2 bk = __half22float2(hh);
    __half2 ll = __float22half2_rn(make_float2(v0 - bk.x, v1 - bk.y));
    h = *(uint32_t*)&hh; l = *(uint32_t*)&ll;
}
__device__ __forceinline__ void mma16(float* d, const uint32_t* a, const uint32_t* b) {
    asm volatile("mma.sync.aligned.m16n8k16.row.col.f32.f16.f16.f32 "
        "{%0,%1,%2,%3}, {%4,%5,%6,%7}, {%8,%9}, {%0,%1,%2,%3};"
        : "+f"(d[0]), "+f"(d[1]), "+f"(d[2]), "+f"(d[3])
        : "r"(a[0]), "r"(a[1]), "r"(a[2]), "r"(a[3]), "r"(b[0]), "r"(b[1]));
}
#define LDM4(r, a)                                                                  \
    asm volatile("ldmatrix.sync.aligned.m8n8.x4.shared.b16 {%0,%1,%2,%3}, [%4];"    \
        : "=r"((r)[0]), "=r"((r)[1]), "=r"((r)[2]), "=r"((r)[3]) : "r"(a))

// =============== K1: fused prep (gathers + prep_B x5 + cls4) ===============
// blocks: [0,64) x1 | [64,80) x2 | [80,84) x3 | [84,85) x4 | [85,725) prep_B | [725,726) cls4
__global__ void __launch_bounds__(256)
prep_all(const float* __restrict__ xyz0,
         const int* __restrict__ idx1, const int* __restrict__ idx2,
         const int* __restrict__ idx3, const int* __restrict__ idx4,
         const float* __restrict__ Wall, const float* __restrict__ ball,
         const float* __restrict__ P4, const float* __restrict__ P3,
         const float* __restrict__ P2, const float* __restrict__ P1,
         const float* __restrict__ P0)
{
    int bid = blockIdx.x, t = threadIdx.x;
    if (bid < 85) {
        const int* idx; float* dst; int base, M;
        if (bid < 64)      { idx = idx1; dst = g_xyz1; base = bid*256;      M = NL1; }
        else if (bid < 80) { idx = idx2; dst = g_xyz2; base = (bid-64)*256; M = NL2; }
        else if (bid < 84) { idx = idx3; dst = g_xyz3; base = (bid-80)*256; M = NL3; }
        else               { idx = idx4; dst = g_xyz4; base = 0;            M = NL4; }
        int i = base + t;
        if (i < M) {
            int s = idx[i];
            dst[i*3+0] = xyz0[s*3+0]; dst[i*3+1] = xyz0[s*3+1]; dst[i*3+2] = xyz0[s*3+2];
        }
    } else if (bid < 725) {
        int lb = bid - 85;
        int lvl = lb >> 7, sub = lb & 127;
        const float* P = lvl == 0 ? P4 : lvl == 1 ? P3 : lvl == 2 ? P2 : lvl == 3 ? P1 : P0;
        int i = sub * 256 + t;
        int reg = i & 1, T = (i >> 1) & 31, ntg = (i >> 6) & 31, s = (i >> 11) & 1, ch = i >> 12;
        int k = ch*32 + s*16 + (T & 3)*2 + reg*8;
        int n = ntg*8 + (T >> 2);
        __half h0, l0, h1, l1;
        splith(P[k*C + n], h0, l0);
        splith(P[(k+1)*C + n], h1, l1);
        g_Bh16[lvl][i] = packh(h0, h1);
        g_Bl16[lvl][i] = packh(l0, l1);
    } else {
        float w0 = Wall[t], w1 = Wall[C+t], w2 = Wall[2*C+t], bb = ball[t];
        float m = -3.4e38f;
        for (int i = 0; i < NL4; i++) {
            float v = fmaf(xyz0[i*3+0], w0, fmaf(xyz0[i*3+1], w1, fmaf(xyz0[i*3+2], w2, bb)));
            m = fmaxf(m, v);
        }
        g_cls4[t] = m;
    }
}

// =============== K2: fused coef (5 levels x 8 blocks) ===============
__global__ void __launch_bounds__(256)
coef_all(const float* __restrict__ Wall, const float* __restrict__ ball,
         const float* __restrict__ W4, const float* __restrict__ b4,
         const float* __restrict__ W3, const float* __restrict__ b3,
         const float* __restrict__ W2, const float* __restrict__ b2,
         const float* __restrict__ W1, const float* __restrict__ b1,
         const float* __restrict__ W0, const float* __restrict__ b0,
         const float* __restrict__ P4, const float* __restrict__ pb4,
         const float* __restrict__ P3, const float* __restrict__ pb3,
         const float* __restrict__ P2, const float* __restrict__ pb2,
         const float* __restrict__ P1, const float* __restrict__ pb1,
         const float* __restrict__ P0, const float* __restrict__ pb0)
{
    __shared__ float red[8][7][32];
    int lvl = blockIdx.x >> 3, blk = blockIdx.x & 7;
    const float* W  = lvl==0 ? W4 : lvl==1 ? W3 : lvl==2 ? W2 : lvl==3 ? W1 : W0;
    const float* b  = lvl==0 ? b4 : lvl==1 ? b3 : lvl==2 ? b2 : lvl==3 ? b1 : b0;
    const float* P  = lvl==0 ? P4 : lvl==1 ? P3 : lvl==2 ? P2 : lvl==3 ? P1 : P0;
    const float* pb = lvl==0 ? pb4: lvl==1 ? pb3: lvl==2 ? pb2: lvl==3 ? pb1: pb0;
    int lvl4 = (lvl == 0);
    float* coef = &g_coef[lvl][0];
    int t = threadIdx.x;
    int nl = t & 31, sl = t >> 5;
    int n = blk * 32 + nl;
    float a0=0,a1=0,a2=0,a3=0,a4=0,a5=0,a6=0;
    for (int c = sl*32; c < sl*32 + 32; c++) {
        float p1 = P[c*C + n], p2 = P[(256 + c)*C + n];
        a0 = fmaf(W[c], p1, a0);
        a1 = fmaf(W[256 + c], p1, a1);
        a2 = fmaf(W[512 + c], p1, a2);
        a3 = fmaf(Wall[c], p2, a3);
        a4 = fmaf(Wall[256 + c], p2, a4);
        a5 = fmaf(Wall[512 + c], p2, a5);
        float bc = b[c] + (lvl4 ? g_cls4[c] : 0.0f);
        a6 = fmaf(bc, p1, fmaf(ball[c], p2, a6));
    }
    red[sl][0][nl]=a0; red[sl][1][nl]=a1; red[sl][2][nl]=a2; red[sl][3][nl]=a3;
    red[sl][4][nl]=a4; red[sl][5][nl]=a5; red[sl][6][nl]=a6;
    __syncthreads();
    if (t < 224) {
        int o = t >> 5, nn = t & 31;
        float s = 0;
        #pragma unroll
        for (int q = 0; q < 8; q++) s += red[q][o][nn];
        if (o == 6) s += pb[blk*32 + nn];
        coef[o*256 + blk*32 + nn] = s;
    }
}

// =============== K3: fused nn (3 maps, 4-way ILP) + pe4 epilogue ===============
// blocks: [0,4) k34 | [4,20) k23 | [20,84) k12 | [84,340) pe4
__global__ void __launch_bounds__(256)
nn_pe4(const float* __restrict__ xyz0, float* __restrict__ out4)
{
    __shared__ float rx[1024], ry[1024], rz[1024], rn[1024];
    int bid = blockIdx.x, t = threadIdx.x;
    if (bid < 84) {
        const float *q, *ref; int Mr, qbase; int* outv;
        if (bid < 4)       { q = g_xyz3; ref = g_xyz4; Mr = NL4; qbase = bid*256;      outv = g_k34; }
        else if (bid < 20) { q = g_xyz2; ref = g_xyz3; Mr = NL3; qbase = (bid-4)*256;  outv = g_k23; }
        else               { q = g_xyz1; ref = g_xyz2; Mr = NL2; qbase = (bid-20)*256; outv = g_k12; }
        int tid = qbase + t;
        float qx = q[tid*3+0], qy = q[tid*3+1], qz = q[tid*3+2];
        float m2x = -2.f*qx, m2y = -2.f*qy, m2z = -2.f*qz;
        float best[4] = {3.4e38f, 3.4e38f, 3.4e38f, 3.4e38f};
        int bi[4] = {0, 0, 0, 0};
        for (int base = 0; base < Mr; base += 1024) {
            int n = min(1024, Mr - base);
            for (int j = t; j < n; j += 256) {
                float x = ref[(base+j)*3+0], y = ref[(base+j)*3+1], z = ref[(base+j)*3+2];
                rx[j]=x; ry[j]=y; rz[j]=z; rn[j] = x*x + y*y + z*z;
            }
            __syncthreads();
            #pragma unroll 2
            for (int j = 0; j < n; j += 4) {
                #pragma unroll
                for (int u = 0; u < 4; u++) {
                    float d = fmaf(m2x, rx[j+u], fmaf(m2y, ry[j+u], fmaf(m2z, rz[j+u], rn[j+u])));
                    if (d < best[u]) { best[u] = d; bi[u] = base + j + u; }
                }
            }
            __syncthreads();
        }
        float bf = best[0]; int bo = bi[0];
        #pragma unroll
        for (int u = 1; u < 4; u++)
            if (best[u] < bf || (best[u] == bf && bi[u] < bo)) { bf = best[u]; bo = bi[u]; }
        outv[tid] = bo;
    } else if (t < 128) {
        int r = bid - 84;
        const float* coef = &g_coef[0][0];
        float dx = g_xyz4[r*3+0], dy = g_xyz4[r*3+1], dz = g_xyz4[r*3+2];
        float x0 = xyz0[r*3+0], y0 = xyz0[r*3+1], z0 = xyz0[r*3+2];
        int c0 = 2*t, c1 = c0 + 1;
        float v0 = coef[6*256+c0] + dx*coef[c0] + dy*coef[256+c0] + dz*coef[512+c0]
                 + x0*coef[3*256+c0] + y0*coef[4*256+c0] + z0*coef[5*256+c0];
        float v1 = coef[6*256+c1] + dx*coef[c1] + dy*coef[256+c1] + dz*coef[512+c1]
                 + x0*coef[3*256+c1] + y0*coef[4*256+c1] + z0*coef[5*256+c1];
        *(float2*)(out4 + (size_t)r*C + c0) = make_float2(v0, v1);
    }
}

// =============== pe GEMM (unchanged from round 9) ===============
#define AL_OFF 2560
#define B_OFF  5120
#define BUFW   9216
#define SMEMB  (2 * BUFW * 4)

__global__ void __launch_bounds__(256, 2)
pe_mma(const int* __restrict__ knn,
       const float* __restrict__ xyzq, const float* __restrict__ xyzr,
       const float* __restrict__ xyz0, const float* __restrict__ pe_prev,
       const uint32_t* __restrict__ Bh, const uint32_t* __restrict__ Bl,
       const float* __restrict__ coef, float* __restrict__ out)
{
    extern __shared__ uint32_t sm[];
    const int t = threadIdx.x, lane = t & 31, wid = t >> 5;
    const int wm = wid & 3, wn = wid >> 2;
    const int rowbase = blockIdx.x * 128;
    const int yb = blockIdx.y;
    const uint32_t sbase = smem_u32(sm);

    const int arow = t & 127, ah2 = t >> 7;
    const int rowg = rowbase + arow;
    const float* prow = pe_prev + (size_t)knn[rowg] * C;

    #define COPY_B(c) do {                                                             \
        const int bw_ = ((c) & 1) * BUFW;                                              \
        const uint32_t* s0_ = Bh + (size_t)(c)*4096 + yb*1024 + t*4;                   \
        const uint32_t* s1_ = Bl + (size_t)(c)*4096 + yb*1024 + t*4;                   \
        _Pragma("unroll")                                                              \
        for (int s_ = 0; s_ < 2; s_++) {                                               \
            asm volatile("cp.async.cg.shared.global [%0], [%1], 16;"                   \
                :: "r"(sbase + 4*(bw_ + B_OFF + s_*1024 + t*4)),                       \
                   "l"(s0_ + s_*2048) : "memory");                                     \
            asm volatile("cp.async.cg.shared.global [%0], [%1], 16;"                   \
                :: "r"(sbase + 4*(bw_ + B_OFF + 2048 + s_*1024 + t*4)),                \
                   "l"(s1_ + s_*2048) : "memory");                                     \
        }                                                                              \
    } while (0)

    #define FILL_A(c) do {                                                             \
        const int bw_ = ((c) & 1) * BUFW;                                              \
        int kg_ = (c)*32 + ah2*16;                                                     \
        float4 v0_ = *(const float4*)(prow + kg_);                                     \
        float4 v1_ = *(const float4*)(prow + kg_ + 4);                                 \
        float4 v2_ = *(const float4*)(prow + kg_ + 8);                                 \
        float4 v3_ = *(const float4*)(prow + kg_ + 12);                                \
        uint32_t hw_[8], lw_[8];                                                       \
        split_pair(v0_.x, v0_.y, hw_[0], lw_[0]);                                      \
        split_pair(v0_.z, v0_.w, hw_[1], lw_[1]);                                      \
        split_pair(v1_.x, v1_.y, hw_[2], lw_[2]);                                      \
        split_pair(v1_.z, v1_.w, hw_[3], lw_[3]);                                      \
        split_pair(v2_.x, v2_.y, hw_[4], lw_[4]);                                      \
        split_pair(v2_.z, v2_.w, hw_[5], lw_[5]);                                      \
        split_pair(v3_.x, v3_.y, hw_[6], lw_[6]);                                      \
        split_pair(v3_.z, v3_.w, hw_[7], lw_[7]);                                      \
        uint4* dh_ = (uint4*)&sm[bw_ + arow*20 + ah2*8];                               \
        dh_[0] = *(uint4*)&hw_[0]; dh_[1] = *(uint4*)&hw_[4];                          \
        uint4* dl_ = (uint4*)&sm[bw_ + AL_OFF + arow*20 + ah2*8];                      \
        dl_[0] = *(uint4*)&lw_[0]; dl_[1] = *(uint4*)&lw_[4];                          \
    } while (0)

    float d[2][8][4];
    #pragma unroll
    for (int i = 0; i < 2; i++)
        #pragma unroll
        for (int j = 0; j < 8; j++)
            #pragma unroll
            for (int q = 0; q < 4; q++) d[i][j][q] = 0.0f;

    COPY_B(0);
    FILL_A(0);
    asm volatile("cp.async.commit_group;" ::: "memory");
    asm volatile("cp.async.wait_group 0;" ::: "memory");
    __syncthreads();

    const int r0 = lane >> 2, c0 = lane & 3;
    const int lr = (lane & 7) + ((lane >> 3) & 1) * 8;
    const int kseg = (lane >> 4) * 4;

    for (int c = 0; c < 8; c++) {
        if (c < 7) {
            COPY_B(c + 1);
            FILL_A(c + 1);
            asm volatile("cp.async.commit_group;" ::: "memory");
        }

        const int bw = (c & 1) * BUFW;
        #pragma unroll
        for (int s = 0; s < 2; s++) {
            uint32_t Afh[2][4], Afl[2][4];
            #pragma unroll
            for (int tmi = 0; tmi < 2; tmi++) {
                uint32_t aw = sbase + 4*(bw + (wm*32 + tmi*16 + lr)*20 + s*8 + kseg);
                LDM4(Afh[tmi], aw);
                LDM4(Afl[tmi], aw + AL_OFF*4);
            }
            uint32_t Bf[8][2];
            #pragma unroll
            for (int nt = 0; nt < 8; nt++) {
                int ntl = wn*8 + nt;
                *(uint2*)Bf[nt] = *(const uint2*)&sm[bw + B_OFF + s*1024 + ntl*64 + lane*2];
            }
            #pragma unroll
            for (int tmi = 0; tmi < 2; tmi++)
                #pragma unroll
                for (int nt = 0; nt < 8; nt++) mma16(d[tmi][nt], Afh[tmi], Bf[nt]);
            #pragma unroll
            for (int tmi = 0; tmi < 2; tmi++)
                #pragma unroll
                for (int nt = 0; nt < 8; nt++) mma16(d[tmi][nt], Afl[tmi], Bf[nt]);
            #pragma unroll
            for (int nt = 0; nt < 8; nt++) {
                int ntl = wn*8 + nt;
                *(uint2*)Bf[nt] = *(const uint2*)&sm[bw + B_OFF + 2048 + s*1024 + ntl*64 + lane*2];
            }
            #pragma unroll
            for (int tmi = 0; tmi < 2; tmi++)
                #pragma unroll
                for (int nt = 0; nt < 8; nt++) mma16(d[tmi][nt], Afh[tmi], Bf[nt]);
        }

        if (c < 7) asm volatile("cp.async.wait_group 0;" ::: "memory");
        __syncthreads();
    }

    float* cfs = (float*)sm;            // [7][128]
    float* dps = (float*)(sm + 896);    // [6][128]
    if (t < 128) {
        int kk = knn[rowg];
        dps[0*128 + t] = xyzq[rowg*3+0] - xyzr[kk*3+0];
        dps[1*128 + t] = xyzq[rowg*3+1] - xyzr[kk*3+1];
        dps[2*128 + t] = xyzq[rowg*3+2] - xyzr[kk*3+2];
        dps[3*128 + t] = xyz0[rowg*3+0];
        dps[4*128 + t] = xyz0[rowg*3+1];
        dps[5*128 + t] = xyz0[rowg*3+2];
    } else {
        int u = t - 128;
        #pragma unroll
        for (int jj = 0; jj < 7; jj++) cfs[jj*128 + u] = coef[jj*256 + yb*128 + u];
    }
    __syncthreads();

    #pragma unroll
    for (int tmi = 0; tmi < 2; tmi++)
        #pragma unroll
        for (int nt = 0; nt < 8; nt++) {
            int rl = wm*32 + tmi*16 + r0;
            int cl = wn*64 + nt*8 + c0*2;
            int rg = rowbase + rl;
            int cg = yb*128 + cl;
            #pragma unroll
            for (int rr = 0; rr < 2; rr++) {
                int rli = rl + rr*8, rgi = rg + rr*8;
                float base0 = cfs[6*128+cl]
                    + dps[0*128+rli]*cfs[0*128+cl] + dps[1*128+rli]*cfs[1*128+cl]
                    + dps[2*128+rli]*cfs[2*128+cl] + dps[3*128+rli]*cfs[3*128+cl]
                    + dps[4*128+rli]*cfs[4*128+cl] + dps[5*128+rli]*cfs[5*128+cl];
                float base1 = cfs[6*128+cl+1]
                    + dps[0*128+rli]*cfs[0*128+cl+1] + dps[1*128+rli]*cfs[1*128+cl+1]
                    + dps[2*128+rli]*cfs[2*128+cl+1] + dps[3*128+rli]*cfs[3*128+cl+1]
                    + dps[4*128+rli]*cfs[4*128+cl+1] + dps[5*128+rli]*cfs[5*128+cl+1];
                *(float2*)(out + (size_t)rgi*C + cg) =
                    make_float2(d[tmi][nt][rr*2+0] + base0, d[tmi][nt][rr*2+1] + base1);
            }
        }
}

// ---------- host ----------
extern "C" void kernel_launch(void* const* d_in, const int* in_sizes, int n_in,
                              void* d_out, int out_size) {
    const float* xyz0 = (const float*)d_in[0];
    const int* idx0 = (const int*)d_in[1];
    const int* idx1 = (const int*)d_in[2];
    const int* idx2 = (const int*)d_in[3];
    const int* idx3 = (const int*)d_in[4];
    const int* idx4 = (const int*)d_in[5];
    const float* W_all = (const float*)d_in[6];
    const float* b_all = (const float*)d_in[7];
    const float* W4 = (const float*)d_in[8];  const float* b4 = (const float*)d_in[9];
    const float* W3 = (const float*)d_in[10]; const float* b3 = (const float*)d_in[11];
    const float* W2 = (const float*)d_in[12]; const float* b2 = (const float*)d_in[13];
    const float* W1 = (const float*)d_in[14]; const float* b1 = (const float*)d_in[15];
    const float* W0 = (const float*)d_in[16]; const float* b0 = (const float*)d_in[17];
    const float* P4 = (const float*)d_in[18]; const float* pb4 = (const float*)d_in[19];
    const float* P3 = (const float*)d_in[20]; const float* pb3 = (const float*)d_in[21];
    const float* P2 = (const float*)d_in[22]; const float* pb2 = (const float*)d_in[23];
    const float* P1 = (const float*)d_in[24]; const float* pb1 = (const float*)d_in[25];
    const float* P0 = (const float*)d_in[26]; const float* pb0 = (const float*)d_in[27];
    float* out = (float*)d_out;

    float *x1, *x2, *x3, *x4, *coef;
    uint32_t *bh, *bl;
    int *k34, *k23, *k12;
    cudaGetSymbolAddress((void**)&x1, g_xyz1);
    cudaGetSymbolAddress((void**)&x2, g_xyz2);
    cudaGetSymbolAddress((void**)&x3, g_xyz3);
    cudaGetSymbolAddress((void**)&x4, g_xyz4);
    cudaGetSymbolAddress((void**)&k34, g_k34);
    cudaGetSymbolAddress((void**)&k23, g_k23);
    cudaGetSymbolAddress((void**)&k12, g_k12);
    cudaGetSymbolAddress((void**)&bh, g_Bh16);
    cudaGetSymbolAddress((void**)&bl, g_Bl16);
    cudaGetSymbolAddress((void**)&coef, g_coef);

    cudaFuncSetAttribute(pe_mma, cudaFuncAttributeMaxDynamicSharedMemorySize, SMEMB);

    prep_all<<<726, 256>>>(xyz0, idx1, idx2, idx3, idx4, W_all, b_all,
                           P4, P3, P2, P1, P0);
    coef_all<<<40, 256>>>(W_all, b_all, W4, b4, W3, b3, W2, b2, W1, b1, W0, b0,
                          P4, pb4, P3, pb3, P2, pb2, P1, pb1, P0, pb0);
    nn_pe4<<<340, 256>>>(xyz0, out + OFF4);

    pe_mma<<<dim3(NL3/128, 2), 256, SMEMB>>>(k34, x3, x4, xyz0, out + OFF4,
        bh + 1*(size_t)32768, bl + 1*(size_t)32768, coef + 1*(size_t)7*256, out + OFF3);
    pe_mma<<<dim3(NL2/128, 2), 256, SMEMB>>>(k23, x2, x3, xyz0, out + OFF3,
        bh + 2*(size_t)32768, bl + 2*(size_t)32768, coef + 2*(size_t)7*256, out + OFF2);
    pe_mma<<<dim3(NL1/128, 2), 256, SMEMB>>>(k12, x1, x2, xyz0, out + OFF2,
        bh + 3*(size_t)32768, bl + 3*(size_t)32768, coef + 3*(size_t)7*256, out + OFF1);
    pe_mma<<<dim3(NL0/128, 2), 256, SMEMB>>>(idx0, xyz0, x1, xyz0, out + OFF1,
        bh + 4*(size_t)32768, bl + 4*(size_t)32768, coef + 4*(size_t)7*256, out + OFF0);
}

// round 11
// speedup vs baseline: 3.4512x; 1.0363x over previous
#include <cuda_runtime.h>
#include <cuda_fp16.h>
#include <cstdint>

#define NL0 65536
#define NL1 16384
#define NL2 4096
#define NL3 1024
#define NL4 256
#define C   256

#define OFF4 0
#define OFF3 (NL4*C)
#define OFF2 (OFF3 + NL3*C)
#define OFF1 (OFF2 + NL2*C)
#define OFF0 (OFF1 + NL1*C)

__device__ uint32_t g_Bh16[5][32768];
__device__ uint32_t g_Bl16[5][32768];
__device__ float g_coef[5][7 * 256];
__device__ float g_cls4[C];
__device__ float g_xyz1[NL1 * 3];
__device__ float g_xyz2[NL2 * 3];
__device__ float g_xyz3[NL3 * 3];
__device__ float g_xyz4[NL4 * 3];
__device__ int   g_k34[NL3];
__device__ int   g_k23[NL2];
__device__ int   g_k12[NL1];

__device__ __forceinline__ uint32_t smem_u32(const void* p) {
    uint32_t a;
    asm("{ .reg .u64 t; cvta.to.shared.u64 t, %1; cvt.u32.u64 %0, t; }" : "=r"(a) : "l"(p));
    return a;
}
__device__ __forceinline__ void splith(float v, __half& h, __half& l) {
    h = __float2half_rn(v);
    l = __float2half_rn(v - __half2float(h));
}
__device__ __forceinline__ uint32_t packh(__half a, __half b) {
    return (uint32_t)__half_as_ushort(a) | ((uint32_t)__half_as_ushort(b) << 16);
}
__device__ __forceinline__ void split_pair(float v0, float v1, uint32_t& h, uint32_t& l) {
    __half2 hh = __float22half2_rn(make_float2(v0, v1));
    float2 bk = __half22float2(hh);
    __half2 ll = __float22half2_rn(make_float2(v0 - bk.x, v1 - bk.y));
    h = *(uint32_t*)&hh; l = *(uint32_t*)&ll;
}
__device__ __forceinline__ void mma16(float* d, const uint32_t* a, const uint32_t* b) {
    asm volatile("mma.sync.aligned.m16n8k16.row.col.f32.f16.f16.f32 "
        "{%0,%1,%2,%3}, {%4,%5,%6,%7}, {%8,%9}, {%0,%1,%2,%3};"
        : "+f"(d[0]), "+f"(d[1]), "+f"(d[2]), "+f"(d[3])
        : "r"(a[0]), "r"(a[1]), "r"(a[2]), "r"(a[3]), "r"(b[0]), "r"(b[1]));
}
#define LDM4(r, a)                                                                  \
    asm volatile("ldmatrix.sync.aligned.m8n8.x4.shared.b16 {%0,%1,%2,%3}, [%4];"    \
        : "=r"((r)[0]), "=r"((r)[1]), "=r"((r)[2]), "=r"((r)[3]) : "r"(a))

// =============== K1: fused prep (gathers + prep_B x5 + cls4) ===============
__global__ void __launch_bounds__(256)
prep_all(const float* __restrict__ xyz0,
         const int* __restrict__ idx1, const int* __restrict__ idx2,
         const int* __restrict__ idx3, const int* __restrict__ idx4,
         const float* __restrict__ Wall, const float* __restrict__ ball,
         const float* __restrict__ P4, const float* __restrict__ P3,
         const float* __restrict__ P2, const float* __restrict__ P1,
         const float* __restrict__ P0)
{
    int bid = blockIdx.x, t = threadIdx.x;
    if (bid < 85) {
        const int* idx; float* dst; int base, M;
        if (bid < 64)      { idx = idx1; dst = g_xyz1; base = bid*256;      M = NL1; }
        else if (bid < 80) { idx = idx2; dst = g_xyz2; base = (bid-64)*256; M = NL2; }
        else if (bid < 84) { idx = idx3; dst = g_xyz3; base = (bid-80)*256; M = NL3; }
        else               { idx = idx4; dst = g_xyz4; base = 0;            M = NL4; }
        int i = base + t;
        if (i < M) {
            int s = idx[i];
            dst[i*3+0] = xyz0[s*3+0]; dst[i*3+1] = xyz0[s*3+1]; dst[i*3+2] = xyz0[s*3+2];
        }
    } else if (bid < 725) {
        int lb = bid - 85;
        int lvl = lb >> 7, sub = lb & 127;
        const float* P = lvl == 0 ? P4 : lvl == 1 ? P3 : lvl == 2 ? P2 : lvl == 3 ? P1 : P0;
        int i = sub * 256 + t;
        int reg = i & 1, T = (i >> 1) & 31, ntg = (i >> 6) & 31, s = (i >> 11) & 1, ch = i >> 12;
        int k = ch*32 + s*16 + (T & 3)*2 + reg*8;
        int n = ntg*8 + (T >> 2);
        __half h0, l0, h1, l1;
        splith(P[k*C + n], h0, l0);
        splith(P[(k+1)*C + n], h1, l1);
        g_Bh16[lvl][i] = packh(h0, h1);
        g_Bl16[lvl][i] = packh(l0, l1);
    } else {
        float w0 = Wall[t], w1 = Wall[C+t], w2 = Wall[2*C+t], bb = ball[t];
        float m = -3.4e38f;
        for (int i = 0; i < NL4; i++) {
            float v = fmaf(xyz0[i*3+0], w0, fmaf(xyz0[i*3+1], w1, fmaf(xyz0[i*3+2], w2, bb)));
            m = fmaxf(m, v);
        }
        g_cls4[t] = m;
    }
}

// =============== K2: fused coef (5 levels x 8 blocks) ===============
__global__ void __launch_bounds__(256)
coef_all(const float* __restrict__ Wall, const float* __restrict__ ball,
         const float* __restrict__ W4, const float* __restrict__ b4,
         const float* __restrict__ W3, const float* __restrict__ b3,
         const float* __restrict__ W2, const float* __restrict__ b2,
         const float* __restrict__ W1, const float* __restrict__ b1,
         const float* __restrict__ W0, const float* __restrict__ b0,
         const float* __restrict__ P4, const float* __restrict__ pb4,
         const float* __restrict__ P3, const float* __restrict__ pb3,
         const float* __restrict__ P2, const float* __restrict__ pb2,
         const float* __restrict__ P1, const float* __restrict__ pb1,
         const float* __restrict__ P0, const float* __restrict__ pb0)
{
    __shared__ float red[8][7][32];
    int lvl = blockIdx.x >> 3, blk = blockIdx.x & 7;
    const float* W  = lvl==0 ? W4 : lvl==1 ? W3 : lvl==2 ? W2 : lvl==3 ? W1 : W0;
    const float* b  = lvl==0 ? b4 : lvl==1 ? b3 : lvl==2 ? b2 : lvl==3 ? b1 : b0;
    const float* P  = lvl==0 ? P4 : lvl==1 ? P3 : lvl==2 ? P2 : lvl==3 ? P1 : P0;
    const float* pb = lvl==0 ? pb4: lvl==1 ? pb3: lvl==2 ? pb2: lvl==3 ? pb1: pb0;
    int lvl4 = (lvl == 0);
    float* coef = &g_coef[lvl][0];
    int t = threadIdx.x;
    int nl = t & 31, sl = t >> 5;
    int n = blk * 32 + nl;
    float a0=0,a1=0,a2=0,a3=0,a4=0,a5=0,a6=0;
    for (int c = sl*32; c < sl*32 + 32; c++) {
        float p1 = P[c*C + n], p2 = P[(256 + c)*C + n];
        a0 = fmaf(W[c], p1, a0);
        a1 = fmaf(W[256 + c], p1, a1);
        a2 = fmaf(W[512 + c], p1, a2);
        a3 = fmaf(Wall[c], p2, a3);
        a4 = fmaf(Wall[256 + c], p2, a4);
        a5 = fmaf(Wall[512 + c], p2, a5);
        float bc = b[c] + (lvl4 ? g_cls4[c] : 0.0f);
        a6 = fmaf(bc, p1, fmaf(ball[c], p2, a6));
    }
    red[sl][0][nl]=a0; red[sl][1][nl]=a1; red[sl][2][nl]=a2; red[sl][3][nl]=a3;
    red[sl][4][nl]=a4; red[sl][5][nl]=a5; red[sl][6][nl]=a6;
    __syncthreads();
    if (t < 224) {
        int o = t >> 5, nn = t & 31;
        float s = 0;
        #pragma unroll
        for (int q = 0; q < 8; q++) s += red[q][o][nn];
        if (o == 6) s += pb[blk*32 + nn];
        coef[o*256 + blk*32 + nn] = s;
    }
}

// =============== K3: fused nn + pe4 ===============
__global__ void __launch_bounds__(256)
nn_pe4(const float* __restrict__ xyz0, float* __restrict__ out4)
{
    __shared__ float rx[1024], ry[1024], rz[1024], rn[1024];
    int bid = blockIdx.x, t = threadIdx.x;
    if (bid < 84) {
        const float *q, *ref; int Mr, qbase; int* outv;
        if (bid < 4)       { q = g_xyz3; ref = g_xyz4; Mr = NL4; qbase = bid*256;      outv = g_k34; }
        else if (bid < 20) { q = g_xyz2; ref = g_xyz3; Mr = NL3; qbase = (bid-4)*256;  outv = g_k23; }
        else               { q = g_xyz1; ref = g_xyz2; Mr = NL2; qbase = (bid-20)*256; outv = g_k12; }
        int tid = qbase + t;
        float qx = q[tid*3+0], qy = q[tid*3+1], qz = q[tid*3+2];
        float m2x = -2.f*qx, m2y = -2.f*qy, m2z = -2.f*qz;
        float best[4] = {3.4e38f, 3.4e38f, 3.4e38f, 3.4e38f};
        int bi[4] = {0, 0, 0, 0};
        for (int base = 0; base < Mr; base += 1024) {
            int n = min(1024, Mr - base);
            for (int j = t; j < n; j += 256) {
                float x = ref[(base+j)*3+0], y = ref[(base+j)*3+1], z = ref[(base+j)*3+2];
                rx[j]=x; ry[j]=y; rz[j]=z; rn[j] = x*x + y*y + z*z;
            }
            __syncthreads();
            #pragma unroll 2
            for (int j = 0; j < n; j += 4) {
                #pragma unroll
                for (int u = 0; u < 4; u++) {
                    float d = fmaf(m2x, rx[j+u], fmaf(m2y, ry[j+u], fmaf(m2z, rz[j+u], rn[j+u])));
                    if (d < best[u]) { best[u] = d; bi[u] = base + j + u; }
                }
            }
            __syncthreads();
        }
        float bf = best[0]; int bo = bi[0];
        #pragma unroll
        for (int u = 1; u < 4; u++)
            if (best[u] < bf || (best[u] == bf && bi[u] < bo)) { bf = best[u]; bo = bi[u]; }
        outv[tid] = bo;
    } else if (t < 128) {
        int r = bid - 84;
        const float* coef = &g_coef[0][0];
        float dx = g_xyz4[r*3+0], dy = g_xyz4[r*3+1], dz = g_xyz4[r*3+2];
        float x0 = xyz0[r*3+0], y0 = xyz0[r*3+1], z0 = xyz0[r*3+2];
        int c0 = 2*t, c1 = c0 + 1;
        float v0 = coef[6*256+c0] + dx*coef[c0] + dy*coef[256+c0] + dz*coef[512+c0]
                 + x0*coef[3*256+c0] + y0*coef[4*256+c0] + z0*coef[5*256+c0];
        float v1 = coef[6*256+c1] + dx*coef[c1] + dy*coef[256+c1] + dz*coef[512+c1]
                 + x0*coef[3*256+c1] + y0*coef[4*256+c1] + z0*coef[5*256+c1];
        *(float2*)(out4 + (size_t)r*C + c0) = make_float2(v0, v1);
    }
}

// =============== pe GEMM: software-pipelined producer ===============
#define AL_OFF 2560
#define B_OFF  5120
#define BUFW   9216
#define SMEMB  (2 * BUFW * 4)

__global__ void __launch_bounds__(256, 2)
pe_mma(const int* __restrict__ knn,
       const float* __restrict__ xyzq, const float* __restrict__ xyzr,
       const float* __restrict__ xyz0, const float* __restrict__ pe_prev,
       const uint32_t* __restrict__ Bh, const uint32_t* __restrict__ Bl,
       const float* __restrict__ coef, float* __restrict__ out)
{
    extern __shared__ uint32_t sm[];
    const int t = threadIdx.x, lane = t & 31, wid = t >> 5;
    const int wm = wid & 3, wn = wid >> 2;
    const int rowbase = blockIdx.x * 128;
    const int yb = blockIdx.y;
    const uint32_t sbase = smem_u32(sm);

    const int arow = t & 127, ah2 = t >> 7;
    const int rowg = rowbase + arow;
    const float* prow = pe_prev + (size_t)knn[rowg] * C;

    #define COPY_B(c) do {                                                             \
        const int bw_ = ((c) & 1) * BUFW;                                              \
        const uint32_t* s0_ = Bh + (size_t)(c)*4096 + yb*1024 + t*4;                   \
        const uint32_t* s1_ = Bl + (size_t)(c)*4096 + yb*1024 + t*4;                   \
        _Pragma("unroll")                                                              \
        for (int s_ = 0; s_ < 2; s_++) {                                               \
            asm volatile("cp.async.cg.shared.global [%0], [%1], 16;"                   \
                :: "r"(sbase + 4*(bw_ + B_OFF + s_*1024 + t*4)),                       \
                   "l"(s0_ + s_*2048) : "memory");                                     \
            asm volatile("cp.async.cg.shared.global [%0], [%1], 16;"                   \
                :: "r"(sbase + 4*(bw_ + B_OFF + 2048 + s_*1024 + t*4)),                \
                   "l"(s1_ + s_*2048) : "memory");                                     \
        }                                                                              \
    } while (0)

    // load A-gather for chunk c into registers (LDG issued here, consumed later)
    #define LOAD_A(c) do {                                                             \
        int kg_ = (c)*32 + ah2*16;                                                     \
        va0 = *(const float4*)(prow + kg_);                                            \
        va1 = *(const float4*)(prow + kg_ + 4);                                        \
        va2 = *(const float4*)(prow + kg_ + 8);                                        \
        va3 = *(const float4*)(prow + kg_ + 12);                                       \
    } while (0)

    // split + store registers into buffer (c)&1
    #define STORE_A(c) do {                                                            \
        const int bw_ = ((c) & 1) * BUFW;                                              \
        uint32_t hw_[8], lw_[8];                                                       \
        split_pair(va0.x, va0.y, hw_[0], lw_[0]);                                      \
        split_pair(va0.z, va0.w, hw_[1], lw_[1]);                                      \
        split_pair(va1.x, va1.y, hw_[2], lw_[2]);                                      \
        split_pair(va1.z, va1.w, hw_[3], lw_[3]);                                      \
        split_pair(va2.x, va2.y, hw_[4], lw_[4]);                                      \
        split_pair(va2.z, va2.w, hw_[5], lw_[5]);                                      \
        split_pair(va3.x, va3.y, hw_[6], lw_[6]);                                      \
        split_pair(va3.z, va3.w, hw_[7], lw_[7]);                                      \
        uint4* dh_ = (uint4*)&sm[bw_ + arow*20 + ah2*8];                               \
        dh_[0] = *(uint4*)&hw_[0]; dh_[1] = *(uint4*)&hw_[4];                          \
        uint4* dl_ = (uint4*)&sm[bw_ + AL_OFF + arow*20 + ah2*8];                      \
        dl_[0] = *(uint4*)&lw_[0]; dl_[1] = *(uint4*)&lw_[4];                          \
    } while (0)

    float d[2][8][4];
    #pragma unroll
    for (int i = 0; i < 2; i++)
        #pragma unroll
        for (int j = 0; j < 8; j++)
            #pragma unroll
            for (int q = 0; q < 4; q++) d[i][j][q] = 0.0f;

    float4 va0, va1, va2, va3;
    LOAD_A(0);
    COPY_B(0);
    asm volatile("cp.async.commit_group;" ::: "memory");
    STORE_A(0);
    asm volatile("cp.async.wait_group 0;" ::: "memory");
    __syncthreads();

    const int r0 = lane >> 2, c0 = lane & 3;
    const int lr = (lane & 7) + ((lane >> 3) & 1) * 8;
    const int kseg = (lane >> 4) * 4;

    for (int c = 0; c < 8; c++) {
        if (c < 7) {
            LOAD_A(c + 1);                       // LDGs in flight during mma
            COPY_B(c + 1);
            asm volatile("cp.async.commit_group;" ::: "memory");
        }

        const int bw = (c & 1) * BUFW;
        #pragma unroll
        for (int s = 0; s < 2; s++) {
            uint32_t Afh[2][4], Afl[2][4];
            #pragma unroll
            for (int tmi = 0; tmi < 2; tmi++) {
                uint32_t aw = sbase + 4*(bw + (wm*32 + tmi*16 + lr)*20 + s*8 + kseg);
                LDM4(Afh[tmi], aw);
                LDM4(Afl[tmi], aw + AL_OFF*4);
            }
            uint32_t Bf[8][2];
            #pragma unroll
            for (int nt = 0; nt < 8; nt++) {
                int ntl = wn*8 + nt;
                *(uint2*)Bf[nt] = *(const uint2*)&sm[bw + B_OFF + s*1024 + ntl*64 + lane*2];
            }
            #pragma unroll
            for (int tmi = 0; tmi < 2; tmi++)
                #pragma unroll
                for (int nt = 0; nt < 8; nt++) mma16(d[tmi][nt], Afh[tmi], Bf[nt]);
            #pragma unroll
            for (int tmi = 0; tmi < 2; tmi++)
                #pragma unroll
                for (int nt = 0; nt < 8; nt++) mma16(d[tmi][nt], Afl[tmi], Bf[nt]);
            #pragma unroll
            for (int nt = 0; nt < 8; nt++) {
                int ntl = wn*8 + nt;
                *(uint2*)Bf[nt] = *(const uint2*)&sm[bw + B_OFF + 2048 + s*1024 + ntl*64 + lane*2];
            }
            #pragma unroll
            for (int tmi = 0; tmi < 2; tmi++)
                #pragma unroll
                for (int nt = 0; nt < 8; nt++) mma16(d[tmi][nt], Afh[tmi], Bf[nt]);
        }

        if (c < 7) {
            STORE_A(c + 1);                      // split + STS after mma
            asm volatile("cp.async.wait_group 0;" ::: "memory");
        }
        __syncthreads();
    }

    float* cfs = (float*)sm;            // [7][128]
    float* dps = (float*)(sm + 896);    // [6][128]
    if (t < 128) {
        int kk = knn[rowg];
        dps[0*128 + t] = xyzq[rowg*3+0] - xyzr[kk*3+0];
        dps[1*128 + t] = xyzq[rowg*3+1] - xyzr[kk*3+1];
        dps[2*128 + t] = xyzq[rowg*3+2] - xyzr[kk*3+2];
        dps[3*128 + t] = xyz0[rowg*3+0];
        dps[4*128 + t] = xyz0[rowg*3+1];
        dps[5*128 + t] = xyz0[rowg*3+2];
    } else {
        int u = t - 128;
        #pragma unroll
        for (int jj = 0; jj < 7; jj++) cfs[jj*128 + u] = coef[jj*256 + yb*128 + u];
    }
    __syncthreads();

    #pragma unroll
    for (int tmi = 0; tmi < 2; tmi++)
        #pragma unroll
        for (int nt = 0; nt < 8; nt++) {
            int rl = wm*32 + tmi*16 + r0;
            int cl = wn*64 + nt*8 + c0*2;
            int rg = rowbase + rl;
            int cg = yb*128 + cl;
            #pragma unroll
            for (int rr = 0; rr < 2; rr++) {
                int rli = rl + rr*8, rgi = rg + rr*8;
                float base0 = cfs[6*128+cl]
                    + dps[0*128+rli]*cfs[0*128+cl] + dps[1*128+rli]*cfs[1*128+cl]
                    + dps[2*128+rli]*cfs[2*128+cl] + dps[3*128+rli]*cfs[3*128+cl]
                    + dps[4*128+rli]*cfs[4*128+cl] + dps[5*128+rli]*cfs[5*128+cl];
                float base1 = cfs[6*128+cl+1]
                    + dps[0*128+rli]*cfs[0*128+cl+1] + dps[1*128+rli]*cfs[1*128+cl+1]
                    + dps[2*128+rli]*cfs[2*128+cl+1] + dps[3*128+rli]*cfs[3*128+cl+1]
                    + dps[4*128+rli]*cfs[4*128+cl+1] + dps[5*128+rli]*cfs[5*128+cl+1];
                *(float2*)(out + (size_t)rgi*C + cg) =
                    make_float2(d[tmi][nt][rr*2+0] + base0, d[tmi][nt][rr*2+1] + base1);
            }
        }
}

// ---------- host ----------
extern "C" void kernel_launch(void* const* d_in, const int* in_sizes, int n_in,
                              void* d_out, int out_size) {
    const float* xyz0 = (const float*)d_in[0];
    const int* idx0 = (const int*)d_in[1];
    const int* idx1 = (const int*)d_in[2];
    const int* idx2 = (const int*)d_in[3];
    const int* idx3 = (const int*)d_in[4];
    const int* idx4 = (const int*)d_in[5];
    const float* W_all = (const float*)d_in[6];
    const float* b_all = (const float*)d_in[7];
    const float* W4 = (const float*)d_in[8];  const float* b4 = (const float*)d_in[9];
    const float* W3 = (const float*)d_in[10]; const float* b3 = (const float*)d_in[11];
    const float* W2 = (const float*)d_in[12]; const float* b2 = (const float*)d_in[13];
    const float* W1 = (const float*)d_in[14]; const float* b1 = (const float*)d_in[15];
    const float* W0 = (const float*)d_in[16]; const float* b0 = (const float*)d_in[17];
    const float* P4 = (const float*)d_in[18]; const float* pb4 = (const float*)d_in[19];
    const float* P3 = (const float*)d_in[20]; const float* pb3 = (const float*)d_in[21];
    const float* P2 = (const float*)d_in[22]; const float* pb2 = (const float*)d_in[23];
    const float* P1 = (const float*)d_in[24]; const float* pb1 = (const float*)d_in[25];
    const float* P0 = (const float*)d_in[26]; const float* pb0 = (const float*)d_in[27];
    float* out = (float*)d_out;

    float *x1, *x2, *x3, *x4, *coef;
    uint32_t *bh, *bl;
    int *k34, *k23, *k12;
    cudaGetSymbolAddress((void**)&x1, g_xyz1);
    cudaGetSymbolAddress((void**)&x2, g_xyz2);
    cudaGetSymbolAddress((void**)&x3, g_xyz3);
    cudaGetSymbolAddress((void**)&x4, g_xyz4);
    cudaGetSymbolAddress((void**)&k34, g_k34);
    cudaGetSymbolAddress((void**)&k23, g_k23);
    cudaGetSymbolAddress((void**)&k12, g_k12);
    cudaGetSymbolAddress((void**)&bh, g_Bh16);
    cudaGetSymbolAddress((void**)&bl, g_Bl16);
    cudaGetSymbolAddress((void**)&coef, g_coef);

    cudaFuncSetAttribute(pe_mma, cudaFuncAttributeMaxDynamicSharedMemorySize, SMEMB);

    prep_all<<<726, 256>>>(xyz0, idx1, idx2, idx3, idx4, W_all, b_all,
                           P4, P3, P2, P1, P0);
    coef_all<<<40, 256>>>(W_all, b_all, W4, b4, W3, b3, W2, b2, W1, b1, W0, b0,
                          P4, pb4, P3, pb3, P2, pb2, P1, pb1, P0, pb0);
    nn_pe4<<<340, 256>>>(xyz0, out + OFF4);

    pe_mma<<<dim3(NL3/128, 2), 256, SMEMB>>>(k34, x3, x4, xyz0, out + OFF4,
        bh + 1*(size_t)32768, bl + 1*(size_t)32768, coef + 1*(size_t)7*256, out + OFF3);
    pe_mma<<<dim3(NL2/128, 2), 256, SMEMB>>>(k23, x2, x3, xyz0, out + OFF3,
        bh + 2*(size_t)32768, bl + 2*(size_t)32768, coef + 2*(size_t)7*256, out + OFF2);
    pe_mma<<<dim3(NL1/128, 2), 256, SMEMB>>>(k12, x1, x2, xyz0, out + OFF2,
        bh + 3*(size_t)32768, bl + 3*(size_t)32768, coef + 3*(size_t)7*256, out + OFF1);
    pe_mma<<<dim3(NL0/128, 2), 256, SMEMB>>>(idx0, xyz0, x1, xyz0, out + OFF1,
        bh + 4*(size_t)32768, bl + 4*(size_t)32768, coef + 4*(size_t)7*256, out + OFF0);
}

// round 13
// speedup vs baseline: 3.9320x; 1.1393x over previous
#include <cuda_runtime.h>
#include <cuda_fp16.h>
#include <cstdint>

#define NL0 65536
#define NL1 16384
#define NL2 4096
#define NL3 1024
#define NL4 256
#define C   256

#define OFF4 0
#define OFF3 (NL4*C)
#define OFF2 (OFF3 + NL3*C)
#define OFF1 (OFF2 + NL2*C)
#define OFF0 (OFF1 + NL1*C)

__device__ uint32_t g_Bh16[5][32768];
__device__ uint32_t g_Bl16[5][32768];
__device__ float g_coef[5][7 * 256];
__device__ float g_cls4[C];
__device__ float g_xyz1[NL1 * 3];
__device__ float g_xyz2[NL2 * 3];
__device__ float g_xyz3[NL3 * 3];
__device__ float g_xyz4[NL4 * 3];
__device__ int   g_k34[NL3];
__device__ int   g_k23[NL2];
__device__ int   g_k12[NL1];

__device__ __forceinline__ uint32_t smem_u32(const void* p) {
    uint32_t a;
    asm("{ .reg .u64 t; cvta.to.shared.u64 t, %1; cvt.u32.u64 %0, t; }" : "=r"(a) : "l"(p));
    return a;
}
__device__ __forceinline__ void splith(float v, __half& h, __half& l) {
    h = __float2half_rn(v);
    l = __float2half_rn(v - __half2float(h));
}
__device__ __forceinline__ uint32_t packh(__half a, __half b) {
    return (uint32_t)__half_as_ushort(a) | ((uint32_t)__half_as_ushort(b) << 16);
}
__device__ __forceinline__ void split_pair(float v0, float v1, uint32_t& h, uint32_t& l) {
    __half2 hh = __float22half2_rn(make_float2(v0, v1));
    float2 bk = __half22float2(hh);
    __half2 ll = __float22half2_rn(make_float2(v0 - bk.x, v1 - bk.y));
    h = *(uint32_t*)&hh; l = *(uint32_t*)&ll;
}
__device__ __forceinline__ void mma16(float* d, const uint32_t* a, const uint32_t* b) {
    asm volatile("mma.sync.aligned.m16n8k16.row.col.f32.f16.f16.f32 "
        "{%0,%1,%2,%3}, {%4,%5,%6,%7}, {%8,%9}, {%0,%1,%2,%3};"
        : "+f"(d[0]), "+f"(d[1]), "+f"(d[2]), "+f"(d[3])
        : "r"(a[0]), "r"(a[1]), "r"(a[2]), "r"(a[3]), "r"(b[0]), "r"(b[1]));
}
#define LDM4(r, a)                                                                  \
    asm volatile("ldmatrix.sync.aligned.m8n8.x4.shared.b16 {%0,%1,%2,%3}, [%4];"    \
        : "=r"((r)[0]), "=r"((r)[1]), "=r"((r)[2]), "=r"((r)[3]) : "r"(a))

// =============== K1: fused prep (gathers + prep_B x5 + cls4) ===============
__global__ void __launch_bounds__(256)
prep_all(const float* __restrict__ xyz0,
         const int* __restrict__ idx1, const int* __restrict__ idx2,
         const int* __restrict__ idx3, const int* __restrict__ idx4,
         const float* __restrict__ Wall, const float* __restrict__ ball,
         const float* __restrict__ P4, const float* __restrict__ P3,
         const float* __restrict__ P2, const float* __restrict__ P1,
         const float* __restrict__ P0)
{
    int bid = blockIdx.x, t = threadIdx.x;
    if (bid < 85) {
        const int* idx; float* dst; int base, M;
        if (bid < 64)      { idx = idx1; dst = g_xyz1; base = bid*256;      M = NL1; }
        else if (bid < 80) { idx = idx2; dst = g_xyz2; base = (bid-64)*256; M = NL2; }
        else if (bid < 84) { idx = idx3; dst = g_xyz3; base = (bid-80)*256; M = NL3; }
        else               { idx = idx4; dst = g_xyz4; base = 0;            M = NL4; }
        int i = base + t;
        if (i < M) {
            int s = idx[i];
            dst[i*3+0] = xyz0[s*3+0]; dst[i*3+1] = xyz0[s*3+1]; dst[i*3+2] = xyz0[s*3+2];
        }
    } else if (bid < 725) {
        int lb = bid - 85;
        int lvl = lb >> 7, sub = lb & 127;
        const float* P = lvl == 0 ? P4 : lvl == 1 ? P3 : lvl == 2 ? P2 : lvl == 3 ? P1 : P0;
        int i = sub * 256 + t;
        int reg = i & 1, T = (i >> 1) & 31, ntg = (i >> 6) & 31, s = (i >> 11) & 1, ch = i >> 12;
        int k = ch*32 + s*16 + (T & 3)*2 + reg*8;
        int n = ntg*8 + (T >> 2);
        __half h0, l0, h1, l1;
        splith(P[k*C + n], h0, l0);
        splith(P[(k+1)*C + n], h1, l1);
        g_Bh16[lvl][i] = packh(h0, h1);
        g_Bl16[lvl][i] = packh(l0, l1);
    } else {
        float w0 = Wall[t], w1 = Wall[C+t], w2 = Wall[2*C+t], bb = ball[t];
        float m = -3.4e38f;
        for (int i = 0; i < NL4; i++) {
            float v = fmaf(xyz0[i*3+0], w0, fmaf(xyz0[i*3+1], w1, fmaf(xyz0[i*3+2], w2, bb)));
            m = fmaxf(m, v);
        }
        g_cls4[t] = m;
    }
}

// =============== K2: fused coef ===============
__global__ void __launch_bounds__(256)
coef_all(const float* __restrict__ Wall, const float* __restrict__ ball,
         const float* __restrict__ W4, const float* __restrict__ b4,
         const float* __restrict__ W3, const float* __restrict__ b3,
         const float* __restrict__ W2, const float* __restrict__ b2,
         const float* __restrict__ W1, const float* __restrict__ b1,
         const float* __restrict__ W0, const float* __restrict__ b0,
         const float* __restrict__ P4, const float* __restrict__ pb4,
         const float* __restrict__ P3, const float* __restrict__ pb3,
         const float* __restrict__ P2, const float* __restrict__ pb2,
         const float* __restrict__ P1, const float* __restrict__ pb1,
         const float* __restrict__ P0, const float* __restrict__ pb0)
{
    __shared__ float red[8][7][32];
    int lvl = blockIdx.x >> 3, blk = blockIdx.x & 7;
    const float* W  = lvl==0 ? W4 : lvl==1 ? W3 : lvl==2 ? W2 : lvl==3 ? W1 : W0;
    const float* b  = lvl==0 ? b4 : lvl==1 ? b3 : lvl==2 ? b2 : lvl==3 ? b1 : b0;
    const float* P  = lvl==0 ? P4 : lvl==1 ? P3 : lvl==2 ? P2 : lvl==3 ? P1 : P0;
    const float* pb = lvl==0 ? pb4: lvl==1 ? pb3: lvl==2 ? pb2: lvl==3 ? pb1: pb0;
    int lvl4 = (lvl == 0);
    float* coef = &g_coef[lvl][0];
    int t = threadIdx.x;
    int nl = t & 31, sl = t >> 5;
    int n = blk * 32 + nl;
    float a0=0,a1=0,a2=0,a3=0,a4=0,a5=0,a6=0;
    for (int c = sl*32; c < sl*32 + 32; c++) {
        float p1 = P[c*C + n], p2 = P[(256 + c)*C + n];
        a0 = fmaf(W[c], p1, a0);
        a1 = fmaf(W[256 + c], p1, a1);
        a2 = fmaf(W[512 + c], p1, a2);
        a3 = fmaf(Wall[c], p2, a3);
        a4 = fmaf(Wall[256 + c], p2, a4);
        a5 = fmaf(Wall[512 + c], p2, a5);
        float bc = b[c] + (lvl4 ? g_cls4[c] : 0.0f);
        a6 = fmaf(bc, p1, fmaf(ball[c], p2, a6));
    }
    red[sl][0][nl]=a0; red[sl][1][nl]=a1; red[sl][2][nl]=a2; red[sl][3][nl]=a3;
    red[sl][4][nl]=a4; red[sl][5][nl]=a5; red[sl][6][nl]=a6;
    __syncthreads();
    if (t < 224) {
        int o = t >> 5, nn = t & 31;
        float s = 0;
        #pragma unroll
        for (int q = 0; q < 8; q++) s += red[q][o][nn];
        if (o == 6) s += pb[blk*32 + nn];
        coef[o*256 + blk*32 + nn] = s;
    }
}

// =============== K3: fused nn + pe4 ===============
__global__ void __launch_bounds__(256)
nn_pe4(const float* __restrict__ xyz0, float* __restrict__ out4)
{
    __shared__ float rx[1024], ry[1024], rz[1024], rn[1024];
    int bid = blockIdx.x, t = threadIdx.x;
    if (bid < 84) {
        const float *q, *ref; int Mr, qbase; int* outv;
        if (bid < 4)       { q = g_xyz3; ref = g_xyz4; Mr = NL4; qbase = bid*256;      outv = g_k34; }
        else if (bid < 20) { q = g_xyz2; ref = g_xyz3; Mr = NL3; qbase = (bid-4)*256;  outv = g_k23; }
        else               { q = g_xyz1; ref = g_xyz2; Mr = NL2; qbase = (bid-20)*256; outv = g_k12; }
        int tid = qbase + t;
        float qx = q[tid*3+0], qy = q[tid*3+1], qz = q[tid*3+2];
        float m2x = -2.f*qx, m2y = -2.f*qy, m2z = -2.f*qz;
        float best[4] = {3.4e38f, 3.4e38f, 3.4e38f, 3.4e38f};
        int bi[4] = {0, 0, 0, 0};
        for (int base = 0; base < Mr; base += 1024) {
            int n = min(1024, Mr - base);
            for (int j = t; j < n; j += 256) {
                float x = ref[(base+j)*3+0], y = ref[(base+j)*3+1], z = ref[(base+j)*3+2];
                rx[j]=x; ry[j]=y; rz[j]=z; rn[j] = x*x + y*y + z*z;
            }
            __syncthreads();
            #pragma unroll 2
            for (int j = 0; j < n; j += 4) {
                #pragma unroll
                for (int u = 0; u < 4; u++) {
                    float d = fmaf(m2x, rx[j+u], fmaf(m2y, ry[j+u], fmaf(m2z, rz[j+u], rn[j+u])));
                    if (d < best[u]) { best[u] = d; bi[u] = base + j + u; }
                }
            }
            __syncthreads();
        }
        float bf = best[0]; int bo = bi[0];
        #pragma unroll
        for (int u = 1; u < 4; u++)
            if (best[u] < bf || (best[u] == bf && bi[u] < bo)) { bf = best[u]; bo = bi[u]; }
        outv[tid] = bo;
    } else if (t < 128) {
        int r = bid - 84;
        const float* coef = &g_coef[0][0];
        float dx = g_xyz4[r*3+0], dy = g_xyz4[r*3+1], dz = g_xyz4[r*3+2];
        float x0 = xyz0[r*3+0], y0 = xyz0[r*3+1], z0 = xyz0[r*3+2];
        int c0 = 2*t, c1 = c0 + 1;
        float v0 = coef[6*256+c0] + dx*coef[c0] + dy*coef[256+c0] + dz*coef[512+c0]
                 + x0*coef[3*256+c0] + y0*coef[4*256+c0] + z0*coef[5*256+c0];
        float v1 = coef[6*256+c1] + dx*coef[c1] + dy*coef[256+c1] + dz*coef[512+c1]
                 + x0*coef[3*256+c1] + y0*coef[4*256+c1] + z0*coef[5*256+c1];
        *(float2*)(out4 + (size_t)r*C + c0) = make_float2(v0, v1);
    }
}

// =============== pe GEMM: M=64 tiles, B triple-buffered ===============
#define A_BUF_W 2560
#define A_LO_W  1280
#define B_BASE  5120
#define B_BUF_W 4096
#define SMEMB   ((B_BASE + 3*B_BUF_W) * 4)   // 69632 bytes

__global__ void __launch_bounds__(256, 2)
pe_mma(const int* __restrict__ knn,
       const float* __restrict__ xyzq, const float* __restrict__ xyzr,
       const float* __restrict__ xyz0, const float* __restrict__ pe_prev,
       const uint32_t* __restrict__ Bh, const uint32_t* __restrict__ Bl,
       const float* __restrict__ coef, float* __restrict__ out)
{
    extern __shared__ uint32_t sm[];
    const int t = threadIdx.x, lane = t & 31, wid = t >> 5;
    const int wm = wid & 1, wn = wid >> 1;          // 2 m-tiles x 4 n-tiles
    const int rowbase = blockIdx.x * 64;
    const int yb = blockIdx.y;
    const uint32_t sbase = smem_u32(sm);

    const int arow = t >> 2, aq = t & 3;            // 4 threads/row, 8 k each
    const int rowg = rowbase + arow;
    const float* prow = pe_prev + (size_t)knn[rowg] * C;

    #define COPY_B(c) do {                                                             \
        const int bb_ = B_BASE + ((c) % 3) * B_BUF_W;                                  \
        const uint32_t* s0_ = Bh + (size_t)(c)*4096 + yb*1024 + t*4;                   \
        const uint32_t* s1_ = Bl + (size_t)(c)*4096 + yb*1024 + t*4;                   \
        _Pragma("unroll")                                                              \
        for (int s_ = 0; s_ < 2; s_++) {                                               \
            asm volatile("cp.async.cg.shared.global [%0], [%1], 16;"                   \
                :: "r"(sbase + 4*(bb_ + s_*1024 + t*4)), "l"(s0_ + s_*2048) : "memory");\
            asm volatile("cp.async.cg.shared.global [%0], [%1], 16;"                   \
                :: "r"(sbase + 4*(bb_ + 2048 + s_*1024 + t*4)), "l"(s1_ + s_*2048) : "memory");\
        }                                                                              \
        asm volatile("cp.async.commit_group;" ::: "memory");                           \
    } while (0)

    #define LOAD_A(c) do {                                                             \
        int kg_ = (c)*32 + aq*8;                                                       \
        va0 = *(const float4*)(prow + kg_);                                            \
        va1 = *(const float4*)(prow + kg_ + 4);                                        \
    } while (0)

    #define STORE_A(c) do {                                                            \
        const int ab_ = ((c) & 1) * A_BUF_W;                                           \
        uint32_t hw_[4], lw_[4];                                                       \
        split_pair(va0.x, va0.y, hw_[0], lw_[0]);                                      \
        split_pair(va0.z, va0.w, hw_[1], lw_[1]);                                      \
        split_pair(va1.x, va1.y, hw_[2], lw_[2]);                                      \
        split_pair(va1.z, va1.w, hw_[3], lw_[3]);                                      \
        *(uint4*)&sm[ab_ + arow*20 + aq*4] = *(uint4*)hw_;                             \
        *(uint4*)&sm[ab_ + A_LO_W + arow*20 + aq*4] = *(uint4*)lw_;                    \
    } while (0)

    float d[2][4][4];
    #pragma unroll
    for (int i = 0; i < 2; i++)
        #pragma unroll
        for (int j = 0; j < 4; j++)
            #pragma unroll
            for (int q = 0; q < 4; q++) d[i][j][q] = 0.0f;

    float4 va0, va1;
    COPY_B(0);
    COPY_B(1);
    LOAD_A(0);
    STORE_A(0);
    asm volatile("cp.async.wait_group 1;" ::: "memory");   // B0 done
    __syncthreads();

    const int r0 = lane >> 2, c0 = lane & 3;
    const int lr = (lane & 7) + ((lane >> 3) & 1) * 8;
    const int kseg = (lane >> 4) * 4;

    for (int c = 0; c < 8; c++) {
        if (c < 6) COPY_B(c + 2);
        if (c < 7) LOAD_A(c + 1);

        const int ab = (c & 1) * A_BUF_W;
        const int bb = B_BASE + (c % 3) * B_BUF_W;
        #pragma unroll
        for (int s = 0; s < 2; s++) {
            uint32_t Afh[2][4], Afl[2][4];
            #pragma unroll
            for (int tmi = 0; tmi < 2; tmi++) {
                uint32_t aw = sbase + 4*(ab + (wm*32 + tmi*16 + lr)*20 + s*8 + kseg);
                LDM4(Afh[tmi], aw);
                LDM4(Afl[tmi], aw + A_LO_W*4);
            }
            uint32_t Bf[4][2];
            #pragma unroll
            for (int nt = 0; nt < 4; nt++) {
                int ntl = wn*4 + nt;
                *(uint2*)Bf[nt] = *(const uint2*)&sm[bb + s*1024 + ntl*64 + lane*2];
            }
            #pragma unroll
            for (int tmi = 0; tmi < 2; tmi++)
                #pragma unroll
                for (int nt = 0; nt < 4; nt++) mma16(d[tmi][nt], Afh[tmi], Bf[nt]);
            #pragma unroll
            for (int tmi = 0; tmi < 2; tmi++)
                #pragma unroll
                for (int nt = 0; nt < 4; nt++) mma16(d[tmi][nt], Afl[tmi], Bf[nt]);
            #pragma unroll
            for (int nt = 0; nt < 4; nt++) {
                int ntl = wn*4 + nt;
                *(uint2*)Bf[nt] = *(const uint2*)&sm[bb + 2048 + s*1024 + ntl*64 + lane*2];
            }
            #pragma unroll
            for (int tmi = 0; tmi < 2; tmi++)
                #pragma unroll
                for (int nt = 0; nt < 4; nt++) mma16(d[tmi][nt], Afh[tmi], Bf[nt]);
        }

        if (c < 7) {
            STORE_A(c + 1);
            if (c < 6) asm volatile("cp.async.wait_group 1;" ::: "memory");
            else       asm volatile("cp.async.wait_group 0;" ::: "memory");
        }
        __syncthreads();
    }

    // ---- self-contained epilogue (FIX: dps[t] must hold data for row rowbase+t) ----
    float* cfs = (float*)sm;            // [7][128]
    float* dps = (float*)(sm + 896);    // [6][64]
    if (t < 64) {
        int rge = rowbase + t;          // row t of this tile (NOT arow!)
        int kk = knn[rge];
        dps[0*64 + t] = xyzq[rge*3+0] - xyzr[kk*3+0];
        dps[1*64 + t] = xyzq[rge*3+1] - xyzr[kk*3+1];
        dps[2*64 + t] = xyzq[rge*3+2] - xyzr[kk*3+2];
        dps[3*64 + t] = xyz0[rge*3+0];
        dps[4*64 + t] = xyz0[rge*3+1];
        dps[5*64 + t] = xyz0[rge*3+2];
    } else if (t >= 128) {
        int u = t - 128;
        #pragma unroll
        for (int jj = 0; jj < 7; jj++) cfs[jj*128 + u] = coef[jj*256 + yb*128 + u];
    }
    __syncthreads();

    #pragma unroll
    for (int tmi = 0; tmi < 2; tmi++)
        #pragma unroll
        for (int nt = 0; nt < 4; nt++) {
            int rl = wm*32 + tmi*16 + r0;
            int cl = wn*32 + nt*8 + c0*2;
            int rg = rowbase + rl;
            int cg = yb*128 + cl;
            #pragma unroll
            for (int rr = 0; rr < 2; rr++) {
                int rli = rl + rr*8, rgi = rg + rr*8;
                float base0 = cfs[6*128+cl]
                    + dps[0*64+rli]*cfs[0*128+cl] + dps[1*64+rli]*cfs[1*128+cl]
                    + dps[2*64+rli]*cfs[2*128+cl] + dps[3*64+rli]*cfs[3*128+cl]
                    + dps[4*64+rli]*cfs[4*128+cl] + dps[5*64+rli]*cfs[5*128+cl];
                float base1 = cfs[6*128+cl+1]
                    + dps[0*64+rli]*cfs[0*128+cl+1] + dps[1*64+rli]*cfs[1*128+cl+1]
                    + dps[2*64+rli]*cfs[2*128+cl+1] + dps[3*64+rli]*cfs[3*128+cl+1]
                    + dps[4*64+rli]*cfs[4*128+cl+1] + dps[5*64+rli]*cfs[5*128+cl+1];
                *(float2*)(out + (size_t)rgi*C + cg) =
                    make_float2(d[tmi][nt][rr*2+0] + base0, d[tmi][nt][rr*2+1] + base1);
            }
        }
}

// ---------- host ----------
extern "C" void kernel_launch(void* const* d_in, const int* in_sizes, int n_in,
                              void* d_out, int out_size) {
    const float* xyz0 = (const float*)d_in[0];
    const int* idx0 = (const int*)d_in[1];
    const int* idx1 = (const int*)d_in[2];
    const int* idx2 = (const int*)d_in[3];
    const int* idx3 = (const int*)d_in[4];
    const int* idx4 = (const int*)d_in[5];
    const float* W_all = (const float*)d_in[6];
    const float* b_all = (const float*)d_in[7];
    const float* W4 = (const float*)d_in[8];  const float* b4 = (const float*)d_in[9];
    const float* W3 = (const float*)d_in[10]; const float* b3 = (const float*)d_in[11];
    const float* W2 = (const float*)d_in[12]; const float* b2 = (const float*)d_in[13];
    const float* W1 = (const float*)d_in[14]; const float* b1 = (const float*)d_in[15];
    const float* W0 = (const float*)d_in[16]; const float* b0 = (const float*)d_in[17];
    const float* P4 = (const float*)d_in[18]; const float* pb4 = (const float*)d_in[19];
    const float* P3 = (const float*)d_in[20]; const float* pb3 = (const float*)d_in[21];
    const float* P2 = (const float*)d_in[22]; const float* pb2 = (const float*)d_in[23];
    const float* P1 = (const float*)d_in[24]; const float* pb1 = (const float*)d_in[25];
    const float* P0 = (const float*)d_in[26]; const float* pb0 = (const float*)d_in[27];
    float* out = (float*)d_out;

    float *x1, *x2, *x3, *x4, *coef;
    uint32_t *bh, *bl;
    int *k34, *k23, *k12;
    cudaGetSymbolAddress((void**)&x1, g_xyz1);
    cudaGetSymbolAddress((void**)&x2, g_xyz2);
    cudaGetSymbolAddress((void**)&x3, g_xyz3);
    cudaGetSymbolAddress((void**)&x4, g_xyz4);
    cudaGetSymbolAddress((void**)&k34, g_k34);
    cudaGetSymbolAddress((void**)&k23, g_k23);
    cudaGetSymbolAddress((void**)&k12, g_k12);
    cudaGetSymbolAddress((void**)&bh, g_Bh16);
    cudaGetSymbolAddress((void**)&bl, g_Bl16);
    cudaGetSymbolAddress((void**)&coef, g_coef);

    cudaFuncSetAttribute(pe_mma, cudaFuncAttributeMaxDynamicSharedMemorySize, SMEMB);

    prep_all<<<726, 256>>>(xyz0, idx1, idx2, idx3, idx4, W_all, b_all,
                           P4, P3, P2, P1, P0);
    coef_all<<<40, 256>>>(W_all, b_all, W4, b4, W3, b3, W2, b2, W1, b1, W0, b0,
                          P4, pb4, P3, pb3, P2, pb2, P1, pb1, P0, pb0);
    nn_pe4<<<340, 256>>>(xyz0, out + OFF4);

    pe_mma<<<dim3(NL3/64, 2), 256, SMEMB>>>(k34, x3, x4, xyz0, out + OFF4,
        bh + 1*(size_t)32768, bl + 1*(size_t)32768, coef + 1*(size_t)7*256, out + OFF3);
    pe_mma<<<dim3(NL2/64, 2), 256, SMEMB>>>(k23, x2, x3, xyz0, out + OFF3,
        bh + 2*(size_t)32768, bl + 2*(size_t)32768, coef + 2*(size_t)7*256, out + OFF2);
    pe_mma<<<dim3(NL1/64, 2), 256, SMEMB>>>(k12, x1, x2, xyz0, out + OFF2,
        bh + 3*(size_t)32768, bl + 3*(size_t)32768, coef + 3*(size_t)7*256, out + OFF1);
    pe_mma<<<dim3(NL0/64, 2), 256, SMEMB>>>(idx0, xyz0, x1, xyz0, out + OFF1,
        bh + 4*(size_t)32768, bl + 4*(size_t)32768, coef + 4*(size_t)7*256, out + OFF0);
}

// round 14
// speedup vs baseline: 4.4553x; 1.1331x over previous
#include <cuda_runtime.h>
#include <cuda_fp16.h>
#include <cstdint>

#define NL0 65536
#define NL1 16384
#define NL2 4096
#define NL3 1024
#define NL4 256
#define C   256

#define OFF4 0
#define OFF3 (NL4*C)
#define OFF2 (OFF3 + NL3*C)
#define OFF1 (OFF2 + NL2*C)
#define OFF0 (OFF1 + NL1*C)

__device__ uint32_t g_Bh16[5][32768];
__device__ uint32_t g_Bl16[5][32768];
__device__ float g_coef[5][7 * 256];
__device__ float g_cls4[C];
__device__ float g_xyz1[NL1 * 3];
__device__ float g_xyz2[NL2 * 3];
__device__ float g_xyz3[NL3 * 3];
__device__ float g_xyz4[NL4 * 3];
__device__ int   g_k34[NL3];
__device__ int   g_k23[NL2];
__device__ int   g_k12[NL1];

__device__ __forceinline__ uint32_t smem_u32(const void* p) {
    uint32_t a;
    asm("{ .reg .u64 t; cvta.to.shared.u64 t, %1; cvt.u32.u64 %0, t; }" : "=r"(a) : "l"(p));
    return a;
}
__device__ __forceinline__ void splith(float v, __half& h, __half& l) {
    h = __float2half_rn(v);
    l = __float2half_rn(v - __half2float(h));
}
__device__ __forceinline__ uint32_t packh(__half a, __half b) {
    return (uint32_t)__half_as_ushort(a) | ((uint32_t)__half_as_ushort(b) << 16);
}
__device__ __forceinline__ void split_pair(float v0, float v1, uint32_t& h, uint32_t& l) {
    __half2 hh = __float22half2_rn(make_float2(v0, v1));
    float2 bk = __half22float2(hh);
    __half2 ll = __float22half2_rn(make_float2(v0 - bk.x, v1 - bk.y));
    h = *(uint32_t*)&hh; l = *(uint32_t*)&ll;
}
__device__ __forceinline__ void mma16(float* d, const uint32_t* a, const uint32_t* b) {
    asm volatile("mma.sync.aligned.m16n8k16.row.col.f32.f16.f16.f32 "
        "{%0,%1,%2,%3}, {%4,%5,%6,%7}, {%8,%9}, {%0,%1,%2,%3};"
        : "+f"(d[0]), "+f"(d[1]), "+f"(d[2]), "+f"(d[3])
        : "r"(a[0]), "r"(a[1]), "r"(a[2]), "r"(a[3]), "r"(b[0]), "r"(b[1]));
}
#define LDM4(r, a)                                                                  \
    asm volatile("ldmatrix.sync.aligned.m8n8.x4.shared.b16 {%0,%1,%2,%3}, [%4];"    \
        : "=r"((r)[0]), "=r"((r)[1]), "=r"((r)[2]), "=r"((r)[3]) : "r"(a))

// =============== K1: fused prep (gathers + prep_B x5 + cls4) ===============
__global__ void __launch_bounds__(256)
prep_all(const float* __restrict__ xyz0,
         const int* __restrict__ idx1, const int* __restrict__ idx2,
         const int* __restrict__ idx3, const int* __restrict__ idx4,
         const float* __restrict__ Wall, const float* __restrict__ ball,
         const float* __restrict__ P4, const float* __restrict__ P3,
         const float* __restrict__ P2, const float* __restrict__ P1,
         const float* __restrict__ P0)
{
    int bid = blockIdx.x, t = threadIdx.x;
    if (bid < 85) {
        const int* idx; float* dst; int base, M;
        if (bid < 64)      { idx = idx1; dst = g_xyz1; base = bid*256;      M = NL1; }
        else if (bid < 80) { idx = idx2; dst = g_xyz2; base = (bid-64)*256; M = NL2; }
        else if (bid < 84) { idx = idx3; dst = g_xyz3; base = (bid-80)*256; M = NL3; }
        else               { idx = idx4; dst = g_xyz4; base = 0;            M = NL4; }
        int i = base + t;
        if (i < M) {
            int s = idx[i];
            dst[i*3+0] = xyz0[s*3+0]; dst[i*3+1] = xyz0[s*3+1]; dst[i*3+2] = xyz0[s*3+2];
        }
    } else if (bid < 725) {
        int lb = bid - 85;
        int lvl = lb >> 7, sub = lb & 127;
        const float* P = lvl == 0 ? P4 : lvl == 1 ? P3 : lvl == 2 ? P2 : lvl == 3 ? P1 : P0;
        int i = sub * 256 + t;
        int reg = i & 1, T = (i >> 1) & 31, ntg = (i >> 6) & 31, s = (i >> 11) & 1, ch = i >> 12;
        int k = ch*32 + s*16 + (T & 3)*2 + reg*8;
        int n = ntg*8 + (T >> 2);
        __half h0, l0, h1, l1;
        splith(P[k*C + n], h0, l0);
        splith(P[(k+1)*C + n], h1, l1);
        g_Bh16[lvl][i] = packh(h0, h1);
        g_Bl16[lvl][i] = packh(l0, l1);
    } else {
        float w0 = Wall[t], w1 = Wall[C+t], w2 = Wall[2*C+t], bb = ball[t];
        float m = -3.4e38f;
        for (int i = 0; i < NL4; i++) {
            float v = fmaf(xyz0[i*3+0], w0, fmaf(xyz0[i*3+1], w1, fmaf(xyz0[i*3+2], w2, bb)));
            m = fmaxf(m, v);
        }
        g_cls4[t] = m;
    }
}

// =============== K2: fused coef (blocks 0-39) + nn (blocks 40-123) ===============
__global__ void __launch_bounds__(256)
coef_nn(const float* __restrict__ Wall, const float* __restrict__ ball,
        const float* __restrict__ W4, const float* __restrict__ b4,
        const float* __restrict__ W3, const float* __restrict__ b3,
        const float* __restrict__ W2, const float* __restrict__ b2,
        const float* __restrict__ W1, const float* __restrict__ b1,
        const float* __restrict__ W0, const float* __restrict__ b0,
        const float* __restrict__ P4, const float* __restrict__ pb4,
        const float* __restrict__ P3, const float* __restrict__ pb3,
        const float* __restrict__ P2, const float* __restrict__ pb2,
        const float* __restrict__ P1, const float* __restrict__ pb1,
        const float* __restrict__ P0, const float* __restrict__ pb0)
{
    __shared__ float shm[4096];        // nn caches (16KB) / coef red (7KB)
    int bid = blockIdx.x, t = threadIdx.x;
    if (bid < 40) {
        float (*red)[7][32] = (float(*)[7][32])shm;
        int lvl = bid >> 3, blk = bid & 7;
        const float* W  = lvl==0 ? W4 : lvl==1 ? W3 : lvl==2 ? W2 : lvl==3 ? W1 : W0;
        const float* b  = lvl==0 ? b4 : lvl==1 ? b3 : lvl==2 ? b2 : lvl==3 ? b1 : b0;
        const float* P  = lvl==0 ? P4 : lvl==1 ? P3 : lvl==2 ? P2 : lvl==3 ? P1 : P0;
        const float* pb = lvl==0 ? pb4: lvl==1 ? pb3: lvl==2 ? pb2: lvl==3 ? pb1: pb0;
        int lvl4 = (lvl == 0);
        float* coef = &g_coef[lvl][0];
        int nl = t & 31, sl = t >> 5;
        int n = blk * 32 + nl;
        float a0=0,a1=0,a2=0,a3=0,a4=0,a5=0,a6=0;
        for (int c = sl*32; c < sl*32 + 32; c++) {
            float p1 = P[c*C + n], p2 = P[(256 + c)*C + n];
            a0 = fmaf(W[c], p1, a0);
            a1 = fmaf(W[256 + c], p1, a1);
            a2 = fmaf(W[512 + c], p1, a2);
            a3 = fmaf(Wall[c], p2, a3);
            a4 = fmaf(Wall[256 + c], p2, a4);
            a5 = fmaf(Wall[512 + c], p2, a5);
            float bc = b[c] + (lvl4 ? g_cls4[c] : 0.0f);
            a6 = fmaf(bc, p1, fmaf(ball[c], p2, a6));
        }
        red[sl][0][nl]=a0; red[sl][1][nl]=a1; red[sl][2][nl]=a2; red[sl][3][nl]=a3;
        red[sl][4][nl]=a4; red[sl][5][nl]=a5; red[sl][6][nl]=a6;
        __syncthreads();
        if (t < 224) {
            int o = t >> 5, nn2 = t & 31;
            float s = 0;
            #pragma unroll
            for (int q = 0; q < 8; q++) s += red[q][o][nn2];
            if (o == 6) s += pb[blk*32 + nn2];
            coef[o*256 + blk*32 + nn2] = s;
        }
    } else {
        int nb = bid - 40;
        float* rx = shm; float* ry = shm + 1024; float* rz = shm + 2048; float* rn = shm + 3072;
        const float *q, *ref; int Mr, qbase; int* outv;
        if (nb < 4)       { q = g_xyz3; ref = g_xyz4; Mr = NL4; qbase = nb*256;      outv = g_k34; }
        else if (nb < 20) { q = g_xyz2; ref = g_xyz3; Mr = NL3; qbase = (nb-4)*256;  outv = g_k23; }
        else              { q = g_xyz1; ref = g_xyz2; Mr = NL2; qbase = (nb-20)*256; outv = g_k12; }
        int tid = qbase + t;
        float qx = q[tid*3+0], qy = q[tid*3+1], qz = q[tid*3+2];
        float m2x = -2.f*qx, m2y = -2.f*qy, m2z = -2.f*qz;
        float best[4] = {3.4e38f, 3.4e38f, 3.4e38f, 3.4e38f};
        int bi[4] = {0, 0, 0, 0};
        for (int base = 0; base < Mr; base += 1024) {
            int n = min(1024, Mr - base);
            for (int j = t; j < n; j += 256) {
                float x = ref[(base+j)*3+0], y = ref[(base+j)*3+1], z = ref[(base+j)*3+2];
                rx[j]=x; ry[j]=y; rz[j]=z; rn[j] = x*x + y*y + z*z;
            }
            __syncthreads();
            #pragma unroll 2
            for (int j = 0; j < n; j += 4) {
                #pragma unroll
                for (int u = 0; u < 4; u++) {
                    float d = fmaf(m2x, rx[j+u], fmaf(m2y, ry[j+u], fmaf(m2z, rz[j+u], rn[j+u])));
                    if (d < best[u]) { best[u] = d; bi[u] = base + j + u; }
                }
            }
            __syncthreads();
        }
        float bf = best[0]; int bo = bi[0];
        #pragma unroll
        for (int u = 1; u < 4; u++)
            if (best[u] < bf || (best[u] == bf && bi[u] < bo)) { bf = best[u]; bo = bi[u]; }
        outv[tid] = bo;
    }
}

// =============== K3: pe4 (no GEMM) ===============
__global__ void __launch_bounds__(128)
pe4_kernel(const float* __restrict__ xyz0, float* __restrict__ out4)
{
    int r = blockIdx.x, t = threadIdx.x;
    const float* coef = &g_coef[0][0];
    float dx = g_xyz4[r*3+0], dy = g_xyz4[r*3+1], dz = g_xyz4[r*3+2];
    float x0 = xyz0[r*3+0], y0 = xyz0[r*3+1], z0 = xyz0[r*3+2];
    int c0 = 2*t, c1 = c0 + 1;
    float v0 = coef[6*256+c0] + dx*coef[c0] + dy*coef[256+c0] + dz*coef[512+c0]
             + x0*coef[3*256+c0] + y0*coef[4*256+c0] + z0*coef[5*256+c0];
    float v1 = coef[6*256+c1] + dx*coef[c1] + dy*coef[256+c1] + dz*coef[512+c1]
             + x0*coef[3*256+c1] + y0*coef[4*256+c1] + z0*coef[5*256+c1];
    *(float2*)(out4 + (size_t)r*C + c0) = make_float2(v0, v1);
}

// =============== pe GEMM: M=64 tiles, k=64 chunks (4 iterations) ===============
// A: 2 buffers x (hi 64x36 | lo 64x36) words. B: 2 buffers x 2 k32-sub-images.
#define A_STRIDE 36
#define A_LO_W   2304
#define A_BUF_W  4608
#define B_BASE   9216
#define B_SUB_W  4096
#define B_BUF_W  8192
#define SMEMB    ((B_BASE + 2*B_BUF_W) * 4)   // 102400 bytes

__global__ void __launch_bounds__(256, 2)
pe_mma(const int* __restrict__ knn,
       const float* __restrict__ xyzq, const float* __restrict__ xyzr,
       const float* __restrict__ xyz0, const float* __restrict__ pe_prev,
       const uint32_t* __restrict__ Bh, const uint32_t* __restrict__ Bl,
       const float* __restrict__ coef, float* __restrict__ out)
{
    extern __shared__ uint32_t sm[];
    const int t = threadIdx.x, lane = t & 31, wid = t >> 5;
    const int wm = wid & 1, wn = wid >> 1;
    const int rowbase = blockIdx.x * 64;
    const int yb = blockIdx.y;
    const uint32_t sbase = smem_u32(sm);

    const int arow = t >> 2, aq = t & 3;        // 4 threads/row, 16 k each
    const int rowg = rowbase + arow;
    const float* prow = pe_prev + (size_t)knn[rowg] * C;

    // copy both k32 sub-images of k64-chunk c into buffer c&1
    #define COPY_B(c) do {                                                             \
        const int bb_ = B_BASE + ((c) & 1) * B_BUF_W;                                  \
        _Pragma("unroll")                                                              \
        for (int j_ = 0; j_ < 2; j_++) {                                               \
            const int cc_ = (c)*2 + j_;                                                \
            const uint32_t* s0_ = Bh + (size_t)cc_*4096 + yb*1024 + t*4;               \
            const uint32_t* s1_ = Bl + (size_t)cc_*4096 + yb*1024 + t*4;               \
            _Pragma("unroll")                                                          \
            for (int s_ = 0; s_ < 2; s_++) {                                           \
                asm volatile("cp.async.cg.shared.global [%0], [%1], 16;"               \
                    :: "r"(sbase + 4*(bb_ + j_*B_SUB_W + s_*1024 + t*4)),              \
                       "l"(s0_ + s_*2048) : "memory");                                 \
                asm volatile("cp.async.cg.shared.global [%0], [%1], 16;"               \
                    :: "r"(sbase + 4*(bb_ + j_*B_SUB_W + 2048 + s_*1024 + t*4)),       \
                       "l"(s1_ + s_*2048) : "memory");                                 \
            }                                                                          \
        }                                                                              \
        asm volatile("cp.async.commit_group;" ::: "memory");                           \
    } while (0)

    #define LOAD_A(c) do {                                                             \
        int kg_ = (c)*64 + aq*16;                                                      \
        va0 = *(const float4*)(prow + kg_);                                            \
        va1 = *(const float4*)(prow + kg_ + 4);                                        \
        va2 = *(const float4*)(prow + kg_ + 8);                                        \
        va3 = *(const float4*)(prow + kg_ + 12);                                       \
    } while (0)

    #define STORE_A(c) do {                                                            \
        const int ab_ = ((c) & 1) * A_BUF_W;                                           \
        uint32_t hw_[8], lw_[8];                                                       \
        split_pair(va0.x, va0.y, hw_[0], lw_[0]);                                      \
        split_pair(va0.z, va0.w, hw_[1], lw_[1]);                                      \
        split_pair(va1.x, va1.y, hw_[2], lw_[2]);                                      \
        split_pair(va1.z, va1.w, hw_[3], lw_[3]);                                      \
        split_pair(va2.x, va2.y, hw_[4], lw_[4]);                                      \
        split_pair(va2.z, va2.w, hw_[5], lw_[5]);                                      \
        split_pair(va3.x, va3.y, hw_[6], lw_[6]);                                      \
        split_pair(va3.z, va3.w, hw_[7], lw_[7]);                                      \
        uint4* dh_ = (uint4*)&sm[ab_ + arow*A_STRIDE + aq*8];                          \
        dh_[0] = *(uint4*)&hw_[0]; dh_[1] = *(uint4*)&hw_[4];                          \
        uint4* dl_ = (uint4*)&sm[ab_ + A_LO_W + arow*A_STRIDE + aq*8];                 \
        dl_[0] = *(uint4*)&lw_[0]; dl_[1] = *(uint4*)&lw_[4];                          \
    } while (0)

    float d[2][4][4];
    #pragma unroll
    for (int i = 0; i < 2; i++)
        #pragma unroll
        for (int j = 0; j < 4; j++)
            #pragma unroll
            for (int q = 0; q < 4; q++) d[i][j][q] = 0.0f;

    float4 va0, va1, va2, va3;
    COPY_B(0);
    LOAD_A(0);
    STORE_A(0);
    asm volatile("cp.async.wait_group 0;" ::: "memory");
    __syncthreads();

    const int r0 = lane >> 2, c0 = lane & 3;
    const int lr = (lane & 7) + ((lane >> 3) & 1) * 8;
    const int kseg = (lane >> 4) * 4;

    for (int c = 0; c < 4; c++) {
        if (c < 3) {
            COPY_B(c + 1);
            LOAD_A(c + 1);
        }

        const int ab = (c & 1) * A_BUF_W;
        const int bb = B_BASE + (c & 1) * B_BUF_W;
        #pragma unroll
        for (int s = 0; s < 4; s++) {
            const int sub = s >> 1, sh = s & 1;
            uint32_t Afh[2][4], Afl[2][4];
            #pragma unroll
            for (int tmi = 0; tmi < 2; tmi++) {
                uint32_t aw = sbase + 4*(ab + (wm*32 + tmi*16 + lr)*A_STRIDE + s*8 + kseg);
                LDM4(Afh[tmi], aw);
                LDM4(Afl[tmi], aw + A_LO_W*4);
            }
            uint32_t Bf[4][2];
            #pragma unroll
            for (int nt = 0; nt < 4; nt++) {
                int ntl = wn*4 + nt;
                *(uint2*)Bf[nt] = *(const uint2*)&sm[bb + sub*B_SUB_W + sh*1024 + ntl*64 + lane*2];
            }
            #pragma unroll
            for (int tmi = 0; tmi < 2; tmi++)
                #pragma unroll
                for (int nt = 0; nt < 4; nt++) mma16(d[tmi][nt], Afh[tmi], Bf[nt]);
            #pragma unroll
            for (int tmi = 0; tmi < 2; tmi++)
                #pragma unroll
                for (int nt = 0; nt < 4; nt++) mma16(d[tmi][nt], Afl[tmi], Bf[nt]);
            #pragma unroll
            for (int nt = 0; nt < 4; nt++) {
                int ntl = wn*4 + nt;
                *(uint2*)Bf[nt] = *(const uint2*)&sm[bb + sub*B_SUB_W + 2048 + sh*1024 + ntl*64 + lane*2];
            }
            #pragma unroll
            for (int tmi = 0; tmi < 2; tmi++)
                #pragma unroll
                for (int nt = 0; nt < 4; nt++) mma16(d[tmi][nt], Afh[tmi], Bf[nt]);
        }

        if (c < 3) {
            STORE_A(c + 1);
            asm volatile("cp.async.wait_group 0;" ::: "memory");
        }
        __syncthreads();
    }

    // ---- self-contained epilogue: dps[t] holds row rowbase+t ----
    float* cfs = (float*)sm;            // [7][128]
    float* dps = (float*)(sm + 896);    // [6][64]
    if (t < 64) {
        int rge = rowbase + t;
        int kk = knn[rge];
        dps[0*64 + t] = xyzq[rge*3+0] - xyzr[kk*3+0];
        dps[1*64 + t] = xyzq[rge*3+1] - xyzr[kk*3+1];
        dps[2*64 + t] = xyzq[rge*3+2] - xyzr[kk*3+2];
        dps[3*64 + t] = xyz0[rge*3+0];
        dps[4*64 + t] = xyz0[rge*3+1];
        dps[5*64 + t] = xyz0[rge*3+2];
    } else if (t >= 128) {
        int u = t - 128;
        #pragma unroll
        for (int jj = 0; jj < 7; jj++) cfs[jj*128 + u] = coef[jj*256 + yb*128 + u];
    }
    __syncthreads();

    #pragma unroll
    for (int tmi = 0; tmi < 2; tmi++)
        #pragma unroll
        for (int nt = 0; nt < 4; nt++) {
            int rl = wm*32 + tmi*16 + r0;
            int cl = wn*32 + nt*8 + c0*2;
            int rg = rowbase + rl;
            int cg = yb*128 + cl;
            #pragma unroll
            for (int rr = 0; rr < 2; rr++) {
                int rli = rl + rr*8, rgi = rg + rr*8;
                float base0 = cfs[6*128+cl]
                    + dps[0*64+rli]*cfs[0*128+cl] + dps[1*64+rli]*cfs[1*128+cl]
                    + dps[2*64+rli]*cfs[2*128+cl] + dps[3*64+rli]*cfs[3*128+cl]
                    + dps[4*64+rli]*cfs[4*128+cl] + dps[5*64+rli]*cfs[5*128+cl];
                float base1 = cfs[6*128+cl+1]
                    + dps[0*64+rli]*cfs[0*128+cl+1] + dps[1*64+rli]*cfs[1*128+cl+1]
                    + dps[2*64+rli]*cfs[2*128+cl+1] + dps[3*64+rli]*cfs[3*128+cl+1]
                    + dps[4*64+rli]*cfs[4*128+cl+1] + dps[5*64+rli]*cfs[5*128+cl+1];
                *(float2*)(out + (size_t)rgi*C + cg) =
                    make_float2(d[tmi][nt][rr*2+0] + base0, d[tmi][nt][rr*2+1] + base1);
            }
        }
}

// ---------- host ----------
extern "C" void kernel_launch(void* const* d_in, const int* in_sizes, int n_in,
                              void* d_out, int out_size) {
    const float* xyz0 = (const float*)d_in[0];
    const int* idx0 = (const int*)d_in[1];
    const int* idx1 = (const int*)d_in[2];
    const int* idx2 = (const int*)d_in[3];
    const int* idx3 = (const int*)d_in[4];
    const int* idx4 = (const int*)d_in[5];
    const float* W_all = (const float*)d_in[6];
    const float* b_all = (const float*)d_in[7];
    const float* W4 = (const float*)d_in[8];  const float* b4 = (const float*)d_in[9];
    const float* W3 = (const float*)d_in[10]; const float* b3 = (const float*)d_in[11];
    const float* W2 = (const float*)d_in[12]; const float* b2 = (const float*)d_in[13];
    const float* W1 = (const float*)d_in[14]; const float* b1 = (const float*)d_in[15];
    const float* W0 = (const float*)d_in[16]; const float* b0 = (const float*)d_in[17];
    const float* P4 = (const float*)d_in[18]; const float* pb4 = (const float*)d_in[19];
    const float* P3 = (const float*)d_in[20]; const float* pb3 = (const float*)d_in[21];
    const float* P2 = (const float*)d_in[22]; const float* pb2 = (const float*)d_in[23];
    const float* P1 = (const float*)d_in[24]; const float* pb1 = (const float*)d_in[25];
    const float* P0 = (const float*)d_in[26]; const float* pb0 = (const float*)d_in[27];
    float* out = (float*)d_out;

    float *x1, *x2, *x3, *x4, *coef;
    uint32_t *bh, *bl;
    int *k34, *k23, *k12;
    cudaGetSymbolAddress((void**)&x1, g_xyz1);
    cudaGetSymbolAddress((void**)&x2, g_xyz2);
    cudaGetSymbolAddress((void**)&x3, g_xyz3);
    cudaGetSymbolAddress((void**)&x4, g_xyz4);
    cudaGetSymbolAddress((void**)&k34, g_k34);
    cudaGetSymbolAddress((void**)&k23, g_k23);
    cudaGetSymbolAddress((void**)&k12, g_k12);
    cudaGetSymbolAddress((void**)&bh, g_Bh16);
    cudaGetSymbolAddress((void**)&bl, g_Bl16);
    cudaGetSymbolAddress((void**)&coef, g_coef);

    cudaFuncSetAttribute(pe_mma, cudaFuncAttributeMaxDynamicSharedMemorySize, SMEMB);

    prep_all<<<726, 256>>>(xyz0, idx1, idx2, idx3, idx4, W_all, b_all,
                           P4, P3, P2, P1, P0);
    coef_nn<<<124, 256>>>(W_all, b_all, W4, b4, W3, b3, W2, b2, W1, b1, W0, b0,
                          P4, pb4, P3, pb3, P2, pb2, P1, pb1, P0, pb0);
    pe4_kernel<<<NL4, 128>>>(xyz0, out + OFF4);

    pe_mma<<<dim3(NL3/64, 2), 256, SMEMB>>>(k34, x3, x4, xyz0, out + OFF4,
        bh + 1*(size_t)32768, bl + 1*(size_t)32768, coef + 1*(size_t)7*256, out + OFF3);
    pe_mma<<<dim3(NL2/64, 2), 256, SMEMB>>>(k23, x2, x3, xyz0, out + OFF3,
        bh + 2*(size_t)32768, bl + 2*(size_t)32768, coef + 2*(size_t)7*256, out + OFF2);
    pe_mma<<<dim3(NL1/64, 2), 256, SMEMB>>>(k12, x1, x2, xyz0, out + OFF2,
        bh + 3*(size_t)32768, bl + 3*(size_t)32768, coef + 3*(size_t)7*256, out + OFF1);
    pe_mma<<<dim3(NL0/64, 2), 256, SMEMB>>>(idx0, xyz0, x1, xyz0, out + OFF1,
        bh + 4*(size_t)32768, bl + 4*(size_t)32768, coef + 4*(size_t)7*256, out + OFF0);
}

// round 15
// speedup vs baseline: 4.5103x; 1.0124x over previous
#include <cuda_runtime.h>
#include <cuda_fp16.h>
#include <cstdint>

#define NL0 65536
#define NL1 16384
#define NL2 4096
#define NL3 1024
#define NL4 256
#define C   256

#define OFF4 0
#define OFF3 (NL4*C)
#define OFF2 (OFF3 + NL3*C)
#define OFF1 (OFF2 + NL2*C)
#define OFF0 (OFF1 + NL1*C)

__device__ uint32_t g_Bh16[5][32768];
__device__ uint32_t g_Bl16[5][32768];
__device__ float g_coef[5][7 * 256];
__device__ float g_cls4[C];
__device__ float g_xyz1[NL1 * 3];
__device__ float g_xyz2[NL2 * 3];
__device__ float g_xyz3[NL3 * 3];
__device__ float g_xyz4[NL4 * 3];
__device__ int   g_k34[NL3];
__device__ int   g_k23[NL2];
__device__ int   g_k12[NL1];

__device__ __forceinline__ uint32_t smem_u32(const void* p) {
    uint32_t a;
    asm("{ .reg .u64 t; cvta.to.shared.u64 t, %1; cvt.u32.u64 %0, t; }" : "=r"(a) : "l"(p));
    return a;
}
__device__ __forceinline__ void splith(float v, __half& h, __half& l) {
    h = __float2half_rn(v);
    l = __float2half_rn(v - __half2float(h));
}
__device__ __forceinline__ uint32_t packh(__half a, __half b) {
    return (uint32_t)__half_as_ushort(a) | ((uint32_t)__half_as_ushort(b) << 16);
}
__device__ __forceinline__ void split_pair(float v0, float v1, uint32_t& h, uint32_t& l) {
    __half2 hh = __float22half2_rn(make_float2(v0, v1));
    float2 bk = __half22float2(hh);
    __half2 ll = __float22half2_rn(make_float2(v0 - bk.x, v1 - bk.y));
    h = *(uint32_t*)&hh; l = *(uint32_t*)&ll;
}
__device__ __forceinline__ void mma16(float* d, const uint32_t* a, const uint32_t* b) {
    asm volatile("mma.sync.aligned.m16n8k16.row.col.f32.f16.f16.f32 "
        "{%0,%1,%2,%3}, {%4,%5,%6,%7}, {%8,%9}, {%0,%1,%2,%3};"
        : "+f"(d[0]), "+f"(d[1]), "+f"(d[2]), "+f"(d[3])
        : "r"(a[0]), "r"(a[1]), "r"(a[2]), "r"(a[3]), "r"(b[0]), "r"(b[1]));
}
#define LDM4(r, a)                                                                  \
    asm volatile("ldmatrix.sync.aligned.m8n8.x4.shared.b16 {%0,%1,%2,%3}, [%4];"    \
        : "=r"((r)[0]), "=r"((r)[1]), "=r"((r)[2]), "=r"((r)[3]) : "r"(a))

// =============== K1: fused prep ===============
__global__ void __launch_bounds__(256)
prep_all(const float* __restrict__ xyz0,
         const int* __restrict__ idx1, const int* __restrict__ idx2,
         const int* __restrict__ idx3, const int* __restrict__ idx4,
         const float* __restrict__ Wall, const float* __restrict__ ball,
         const float* __restrict__ P4, const float* __restrict__ P3,
         const float* __restrict__ P2, const float* __restrict__ P1,
         const float* __restrict__ P0)
{
    int bid = blockIdx.x, t = threadIdx.x;
    if (bid < 85) {
        const int* idx; float* dst; int base, M;
        if (bid < 64)      { idx = idx1; dst = g_xyz1; base = bid*256;      M = NL1; }
        else if (bid < 80) { idx = idx2; dst = g_xyz2; base = (bid-64)*256; M = NL2; }
        else if (bid < 84) { idx = idx3; dst = g_xyz3; base = (bid-80)*256; M = NL3; }
        else               { idx = idx4; dst = g_xyz4; base = 0;            M = NL4; }
        int i = base + t;
        if (i < M) {
            int s = idx[i];
            dst[i*3+0] = xyz0[s*3+0]; dst[i*3+1] = xyz0[s*3+1]; dst[i*3+2] = xyz0[s*3+2];
        }
    } else if (bid < 725) {
        int lb = bid - 85;
        int lvl = lb >> 7, sub = lb & 127;
        const float* P = lvl == 0 ? P4 : lvl == 1 ? P3 : lvl == 2 ? P2 : lvl == 3 ? P1 : P0;
        int i = sub * 256 + t;
        int reg = i & 1, T = (i >> 1) & 31, ntg = (i >> 6) & 31, s = (i >> 11) & 1, ch = i >> 12;
        int k = ch*32 + s*16 + (T & 3)*2 + reg*8;
        int n = ntg*8 + (T >> 2);
        __half h0, l0, h1, l1;
        splith(P[k*C + n], h0, l0);
        splith(P[(k+1)*C + n], h1, l1);
        g_Bh16[lvl][i] = packh(h0, h1);
        g_Bl16[lvl][i] = packh(l0, l1);
    } else {
        float w0 = Wall[t], w1 = Wall[C+t], w2 = Wall[2*C+t], bb = ball[t];
        float m = -3.4e38f;
        for (int i = 0; i < NL4; i++) {
            float v = fmaf(xyz0[i*3+0], w0, fmaf(xyz0[i*3+1], w1, fmaf(xyz0[i*3+2], w2, bb)));
            m = fmaxf(m, v);
        }
        g_cls4[t] = m;
    }
}

// =============== K2: fused coef + nn ===============
__global__ void __launch_bounds__(256)
coef_nn(const float* __restrict__ Wall, const float* __restrict__ ball,
        const float* __restrict__ W4, const float* __restrict__ b4,
        const float* __restrict__ W3, const float* __restrict__ b3,
        const float* __restrict__ W2, const float* __restrict__ b2,
        const float* __restrict__ W1, const float* __restrict__ b1,
        const float* __restrict__ W0, const float* __restrict__ b0,
        const float* __restrict__ P4, const float* __restrict__ pb4,
        const float* __restrict__ P3, const float* __restrict__ pb3,
        const float* __restrict__ P2, const float* __restrict__ pb2,
        const float* __restrict__ P1, const float* __restrict__ pb1,
        const float* __restrict__ P0, const float* __restrict__ pb0)
{
    __shared__ float shm[4096];
    int bid = blockIdx.x, t = threadIdx.x;
    if (bid < 40) {
        float (*red)[7][32] = (float(*)[7][32])shm;
        int lvl = bid >> 3, blk = bid & 7;
        const float* W  = lvl==0 ? W4 : lvl==1 ? W3 : lvl==2 ? W2 : lvl==3 ? W1 : W0;
        const float* b  = lvl==0 ? b4 : lvl==1 ? b3 : lvl==2 ? b2 : lvl==3 ? b1 : b0;
        const float* P  = lvl==0 ? P4 : lvl==1 ? P3 : lvl==2 ? P2 : lvl==3 ? P1 : P0;
        const float* pb = lvl==0 ? pb4: lvl==1 ? pb3: lvl==2 ? pb2: lvl==3 ? pb1: pb0;
        int lvl4 = (lvl == 0);
        float* coef = &g_coef[lvl][0];
        int nl = t & 31, sl = t >> 5;
        int n = blk * 32 + nl;
        float a0=0,a1=0,a2=0,a3=0,a4=0,a5=0,a6=0;
        for (int c = sl*32; c < sl*32 + 32; c++) {
            float p1 = P[c*C + n], p2 = P[(256 + c)*C + n];
            a0 = fmaf(W[c], p1, a0);
            a1 = fmaf(W[256 + c], p1, a1);
            a2 = fmaf(W[512 + c], p1, a2);
            a3 = fmaf(Wall[c], p2, a3);
            a4 = fmaf(Wall[256 + c], p2, a4);
            a5 = fmaf(Wall[512 + c], p2, a5);
            float bc = b[c] + (lvl4 ? g_cls4[c] : 0.0f);
            a6 = fmaf(bc, p1, fmaf(ball[c], p2, a6));
        }
        red[sl][0][nl]=a0; red[sl][1][nl]=a1; red[sl][2][nl]=a2; red[sl][3][nl]=a3;
        red[sl][4][nl]=a4; red[sl][5][nl]=a5; red[sl][6][nl]=a6;
        __syncthreads();
        if (t < 224) {
            int o = t >> 5, nn2 = t & 31;
            float s = 0;
            #pragma unroll
            for (int q = 0; q < 8; q++) s += red[q][o][nn2];
            if (o == 6) s += pb[blk*32 + nn2];
            coef[o*256 + blk*32 + nn2] = s;
        }
    } else {
        int nb = bid - 40;
        float* rx = shm; float* ry = shm + 1024; float* rz = shm + 2048; float* rn = shm + 3072;
        const float *q, *ref; int Mr, qbase; int* outv;
        if (nb < 4)       { q = g_xyz3; ref = g_xyz4; Mr = NL4; qbase = nb*256;      outv = g_k34; }
        else if (nb < 20) { q = g_xyz2; ref = g_xyz3; Mr = NL3; qbase = (nb-4)*256;  outv = g_k23; }
        else              { q = g_xyz1; ref = g_xyz2; Mr = NL2; qbase = (nb-20)*256; outv = g_k12; }
        int tid = qbase + t;
        float qx = q[tid*3+0], qy = q[tid*3+1], qz = q[tid*3+2];
        float m2x = -2.f*qx, m2y = -2.f*qy, m2z = -2.f*qz;
        float best[4] = {3.4e38f, 3.4e38f, 3.4e38f, 3.4e38f};
        int bi[4] = {0, 0, 0, 0};
        for (int base = 0; base < Mr; base += 1024) {
            int n = min(1024, Mr - base);
            for (int j = t; j < n; j += 256) {
                float x = ref[(base+j)*3+0], y = ref[(base+j)*3+1], z = ref[(base+j)*3+2];
                rx[j]=x; ry[j]=y; rz[j]=z; rn[j] = x*x + y*y + z*z;
            }
            __syncthreads();
            #pragma unroll 2
            for (int j = 0; j < n; j += 4) {
                #pragma unroll
                for (int u = 0; u < 4; u++) {
                    float d = fmaf(m2x, rx[j+u], fmaf(m2y, ry[j+u], fmaf(m2z, rz[j+u], rn[j+u])));
                    if (d < best[u]) { best[u] = d; bi[u] = base + j + u; }
                }
            }
            __syncthreads();
        }
        float bf = best[0]; int bo = bi[0];
        #pragma unroll
        for (int u = 1; u < 4; u++)
            if (best[u] < bf || (best[u] == bf && bi[u] < bo)) { bf = best[u]; bo = bi[u]; }
        outv[tid] = bo;
    }
}

// =============== K3: pe4 ===============
__global__ void __launch_bounds__(128)
pe4_kernel(const float* __restrict__ xyz0, float* __restrict__ out4)
{
    int r = blockIdx.x, t = threadIdx.x;
    const float* coef = &g_coef[0][0];
    float dx = g_xyz4[r*3+0], dy = g_xyz4[r*3+1], dz = g_xyz4[r*3+2];
    float x0 = xyz0[r*3+0], y0 = xyz0[r*3+1], z0 = xyz0[r*3+2];
    int c0 = 2*t, c1 = c0 + 1;
    float v0 = coef[6*256+c0] + dx*coef[c0] + dy*coef[256+c0] + dz*coef[512+c0]
             + x0*coef[3*256+c0] + y0*coef[4*256+c0] + z0*coef[5*256+c0];
    float v1 = coef[6*256+c1] + dx*coef[c1] + dy*coef[256+c1] + dz*coef[512+c1]
             + x0*coef[3*256+c1] + y0*coef[4*256+c1] + z0*coef[5*256+c1];
    *(float2*)(out4 + (size_t)r*C + c0) = make_float2(v0, v1);
}

// =============== pe GEMM: template TM (m16-tiles per warp-row) ===============
// TM=2: M=64/CTA (L1,L0).  TM=1: M=32/CTA (L3,L2).
#define A_STRIDE 36
#define B_SUB_W  4096
#define B_BUF_W  8192

template<int TM>
__global__ void __launch_bounds__(256, 2)
pe_mma(const int* __restrict__ knn,
       const float* __restrict__ xyzq, const float* __restrict__ xyzr,
       const float* __restrict__ xyz0, const float* __restrict__ pe_prev,
       const uint32_t* __restrict__ Bh, const uint32_t* __restrict__ Bl,
       const float* __restrict__ coef, float* __restrict__ out)
{
    constexpr int MROWS  = TM * 32;
    constexpr int A_LO_W = MROWS * A_STRIDE;
    constexpr int A_BUF_W = 2 * A_LO_W;
    constexpr int B_BASE  = 2 * A_BUF_W;

    extern __shared__ uint32_t sm[];
    const int t = threadIdx.x, lane = t & 31, wid = t >> 5;
    const int wm = wid & 1, wn = wid >> 1;
    const int rowbase = blockIdx.x * MROWS;
    const int yb = blockIdx.y;
    const uint32_t sbase = smem_u32(sm);

    // A fill: TM=2 -> 4 thr/row x 16 k; TM=1 -> 8 thr/row x 8 k
    const int arow = (TM == 2) ? (t >> 2) : (t >> 3);
    const int aq   = (TM == 2) ? (t & 3) : (t & 7);
    const int rowg = rowbase + arow;
    const float* prow = pe_prev + (size_t)knn[rowg] * C;

    #define COPY_B(c) do {                                                             \
        const int bb_ = B_BASE + ((c) & 1) * B_BUF_W;                                  \
        _Pragma("unroll")                                                              \
        for (int j_ = 0; j_ < 2; j_++) {                                               \
            const int cc_ = (c)*2 + j_;                                                \
            const uint32_t* s0_ = Bh + (size_t)cc_*4096 + yb*1024 + t*4;               \
            const uint32_t* s1_ = Bl + (size_t)cc_*4096 + yb*1024 + t*4;               \
            _Pragma("unroll")                                                          \
            for (int s_ = 0; s_ < 2; s_++) {                                           \
                asm volatile("cp.async.cg.shared.global [%0], [%1], 16;"               \
                    :: "r"(sbase + 4*(bb_ + j_*B_SUB_W + s_*1024 + t*4)),              \
                       "l"(s0_ + s_*2048) : "memory");                                 \
                asm volatile("cp.async.cg.shared.global [%0], [%1], 16;"               \
                    :: "r"(sbase + 4*(bb_ + j_*B_SUB_W + 2048 + s_*1024 + t*4)),       \
                       "l"(s1_ + s_*2048) : "memory");                                 \
            }                                                                          \
        }                                                                              \
        asm volatile("cp.async.commit_group;" ::: "memory");                           \
    } while (0)

    float4 va0, va1, va2, va3;
    #define LOAD_A(c) do {                                                             \
        if (TM == 2) {                                                                 \
            int kg_ = (c)*64 + aq*16;                                                  \
            va0 = *(const float4*)(prow + kg_);                                        \
            va1 = *(const float4*)(prow + kg_ + 4);                                    \
            va2 = *(const float4*)(prow + kg_ + 8);                                    \
            va3 = *(const float4*)(prow + kg_ + 12);                                   \
        } else {                                                                       \
            int kg_ = (c)*64 + aq*8;                                                   \
            va0 = *(const float4*)(prow + kg_);                                        \
            va1 = *(const float4*)(prow + kg_ + 4);                                    \
        }                                                                              \
    } while (0)

    #define STORE_A(c) do {                                                            \
        const int ab_ = ((c) & 1) * A_BUF_W;                                           \
        if (TM == 2) {                                                                 \
            uint32_t hw_[8], lw_[8];                                                   \
            split_pair(va0.x, va0.y, hw_[0], lw_[0]);                                  \
            split_pair(va0.z, va0.w, hw_[1], lw_[1]);                                  \
            split_pair(va1.x, va1.y, hw_[2], lw_[2]);                                  \
            split_pair(va1.z, va1.w, hw_[3], lw_[3]);                                  \
            split_pair(va2.x, va2.y, hw_[4], lw_[4]);                                  \
            split_pair(va2.z, va2.w, hw_[5], lw_[5]);                                  \
            split_pair(va3.x, va3.y, hw_[6], lw_[6]);                                  \
            split_pair(va3.z, va3.w, hw_[7], lw_[7]);                                  \
            uint4* dh_ = (uint4*)&sm[ab_ + arow*A_STRIDE + aq*8];                      \
            dh_[0] = *(uint4*)&hw_[0]; dh_[1] = *(uint4*)&hw_[4];                      \
            uint4* dl_ = (uint4*)&sm[ab_ + A_LO_W + arow*A_STRIDE + aq*8];             \
            dl_[0] = *(uint4*)&lw_[0]; dl_[1] = *(uint4*)&lw_[4];                      \
        } else {                                                                       \
            uint32_t hw_[4], lw_[4];                                                   \
            split_pair(va0.x, va0.y, hw_[0], lw_[0]);                                  \
            split_pair(va0.z, va0.w, hw_[1], lw_[1]);                                  \
            split_pair(va1.x, va1.y, hw_[2], lw_[2]);                                  \
            split_pair(va1.z, va1.w, hw_[3], lw_[3]);                                  \
            *(uint4*)&sm[ab_ + arow*A_STRIDE + aq*4] = *(uint4*)hw_;                   \
            *(uint4*)&sm[ab_ + A_LO_W + arow*A_STRIDE + aq*4] = *(uint4*)lw_;          \
        }                                                                              \
    } while (0)

    float d[TM][4][4];
    #pragma unroll
    for (int i = 0; i < TM; i++)
        #pragma unroll
        for (int j = 0; j < 4; j++)
            #pragma unroll
            for (int q = 0; q < 4; q++) d[i][j][q] = 0.0f;

    COPY_B(0);
    LOAD_A(0);
    STORE_A(0);
    asm volatile("cp.async.wait_group 0;" ::: "memory");
    __syncthreads();

    const int r0 = lane >> 2, c0 = lane & 3;
    const int lr = (lane & 7) + ((lane >> 3) & 1) * 8;
    const int kseg = (lane >> 4) * 4;

    for (int c = 0; c < 4; c++) {
        if (c < 3) {
            COPY_B(c + 1);
            LOAD_A(c + 1);
        }

        const int ab = (c & 1) * A_BUF_W;
        const int bb = B_BASE + (c & 1) * B_BUF_W;
        #pragma unroll
        for (int s = 0; s < 4; s++) {
            const int sub = s >> 1, sh = s & 1;
            uint32_t Afh[TM][4], Afl[TM][4];
            #pragma unroll
            for (int tmi = 0; tmi < TM; tmi++) {
                uint32_t aw = sbase + 4*(ab + (wm*(TM*16) + tmi*16 + lr)*A_STRIDE + s*8 + kseg);
                LDM4(Afh[tmi], aw);
                LDM4(Afl[tmi], aw + A_LO_W*4);
            }
            uint32_t Bf[4][2];
            #pragma unroll
            for (int nt = 0; nt < 4; nt++) {
                int ntl = wn*4 + nt;
                *(uint2*)Bf[nt] = *(const uint2*)&sm[bb + sub*B_SUB_W + sh*1024 + ntl*64 + lane*2];
            }
            #pragma unroll
            for (int tmi = 0; tmi < TM; tmi++)
                #pragma unroll
                for (int nt = 0; nt < 4; nt++) mma16(d[tmi][nt], Afh[tmi], Bf[nt]);
            #pragma unroll
            for (int tmi = 0; tmi < TM; tmi++)
                #pragma unroll
                for (int nt = 0; nt < 4; nt++) mma16(d[tmi][nt], Afl[tmi], Bf[nt]);
            #pragma unroll
            for (int nt = 0; nt < 4; nt++) {
                int ntl = wn*4 + nt;
                *(uint2*)Bf[nt] = *(const uint2*)&sm[bb + sub*B_SUB_W + 2048 + sh*1024 + ntl*64 + lane*2];
            }
            #pragma unroll
            for (int tmi = 0; tmi < TM; tmi++)
                #pragma unroll
                for (int nt = 0; nt < 4; nt++) mma16(d[tmi][nt], Afh[tmi], Bf[nt]);
        }

        if (c < 3) {
            STORE_A(c + 1);
            asm volatile("cp.async.wait_group 0;" ::: "memory");
        }
        __syncthreads();
    }

    // ---- epilogue: dps[t] holds row rowbase+t ----
    float* cfs = (float*)sm;                 // [7][128]
    float* dps = (float*)(sm + 896);         // [6][MROWS]
    if (t < MROWS) {
        int rge = rowbase + t;
        int kk = knn[rge];
        dps[0*MROWS + t] = xyzq[rge*3+0] - xyzr[kk*3+0];
        dps[1*MROWS + t] = xyzq[rge*3+1] - xyzr[kk*3+1];
        dps[2*MROWS + t] = xyzq[rge*3+2] - xyzr[kk*3+2];
        dps[3*MROWS + t] = xyz0[rge*3+0];
        dps[4*MROWS + t] = xyz0[rge*3+1];
        dps[5*MROWS + t] = xyz0[rge*3+2];
    } else if (t >= 128) {
        int u = t - 128;
        #pragma unroll
        for (int jj = 0; jj < 7; jj++) cfs[jj*128 + u] = coef[jj*256 + yb*128 + u];
    }
    __syncthreads();

    #pragma unroll
    for (int tmi = 0; tmi < TM; tmi++)
        #pragma unroll
        for (int nt = 0; nt < 4; nt++) {
            int rl = wm*(TM*16) + tmi*16 + r0;
            int cl = wn*32 + nt*8 + c0*2;
            int rg = rowbase + rl;
            int cg = yb*128 + cl;
            #pragma unroll
            for (int rr = 0; rr < 2; rr++) {
                int rli = rl + rr*8, rgi = rg + rr*8;
                float base0 = cfs[6*128+cl]
                    + dps[0*MROWS+rli]*cfs[0*128+cl] + dps[1*MROWS+rli]*cfs[1*128+cl]
                    + dps[2*MROWS+rli]*cfs[2*128+cl] + dps[3*MROWS+rli]*cfs[3*128+cl]
                    + dps[4*MROWS+rli]*cfs[4*128+cl] + dps[5*MROWS+rli]*cfs[5*128+cl];
                float base1 = cfs[6*128+cl+1]
                    + dps[0*MROWS+rli]*cfs[0*128+cl+1] + dps[1*MROWS+rli]*cfs[1*128+cl+1]
                    + dps[2*MROWS+rli]*cfs[2*128+cl+1] + dps[3*MROWS+rli]*cfs[3*128+cl+1]
                    + dps[4*MROWS+rli]*cfs[4*128+cl+1] + dps[5*MROWS+rli]*cfs[5*128+cl+1];
                *(float2*)(out + (size_t)rgi*C + cg) =
                    make_float2(d[tmi][nt][rr*2+0] + base0, d[tmi][nt][rr*2+1] + base1);
            }
        }
}

#define SMEMB2 ((2*2*64*A_STRIDE + 2*B_BUF_W) * 4)      // TM=2: 102400 B
#define SMEMB1 ((2*2*32*A_STRIDE + 2*B_BUF_W) * 4)      // TM=1:  83968 B

// ---------- host ----------
extern "C" void kernel_launch(void* const* d_in, const int* in_sizes, int n_in,
                              void* d_out, int out_size) {
    const float* xyz0 = (const float*)d_in[0];
    const int* idx0 = (const int*)d_in[1];
    const int* idx1 = (const int*)d_in[2];
    const int* idx2 = (const int*)d_in[3];
    const int* idx3 = (const int*)d_in[4];
    const int* idx4 = (const int*)d_in[5];
    const float* W_all = (const float*)d_in[6];
    const float* b_all = (const float*)d_in[7];
    const float* W4 = (const float*)d_in[8];  const float* b4 = (const float*)d_in[9];
    const float* W3 = (const float*)d_in[10]; const float* b3 = (const float*)d_in[11];
    const float* W2 = (const float*)d_in[12]; const float* b2 = (const float*)d_in[13];
    const float* W1 = (const float*)d_in[14]; const float* b1 = (const float*)d_in[15];
    const float* W0 = (const float*)d_in[16]; const float* b0 = (const float*)d_in[17];
    const float* P4 = (const float*)d_in[18]; const float* pb4 = (const float*)d_in[19];
    const float* P3 = (const float*)d_in[20]; const float* pb3 = (const float*)d_in[21];
    const float* P2 = (const float*)d_in[22]; const float* pb2 = (const float*)d_in[23];
    const float* P1 = (const float*)d_in[24]; const float* pb1 = (const float*)d_in[25];
    const float* P0 = (const float*)d_in[26]; const float* pb0 = (const float*)d_in[27];
    float* out = (float*)d_out;

    float *x1, *x2, *x3, *x4, *coef;
    uint32_t *bh, *bl;
    int *k34, *k23, *k12;
    cudaGetSymbolAddress((void**)&x1, g_xyz1);
    cudaGetSymbolAddress((void**)&x2, g_xyz2);
    cudaGetSymbolAddress((void**)&x3, g_xyz3);
    cudaGetSymbolAddress((void**)&x4, g_xyz4);
    cudaGetSymbolAddress((void**)&k34, g_k34);
    cudaGetSymbolAddress((void**)&k23, g_k23);
    cudaGetSymbolAddress((void**)&k12, g_k12);
    cudaGetSymbolAddress((void**)&bh, g_Bh16);
    cudaGetSymbolAddress((void**)&bl, g_Bl16);
    cudaGetSymbolAddress((void**)&coef, g_coef);

    cudaFuncSetAttribute(pe_mma<2>, cudaFuncAttributeMaxDynamicSharedMemorySize, SMEMB2);
    cudaFuncSetAttribute(pe_mma<1>, cudaFuncAttributeMaxDynamicSharedMemorySize, SMEMB1);

    prep_all<<<726, 256>>>(xyz0, idx1, idx2, idx3, idx4, W_all, b_all,
                           P4, P3, P2, P1, P0);
    coef_nn<<<124, 256>>>(W_all, b_all, W4, b4, W3, b3, W2, b2, W1, b1, W0, b0,
                          P4, pb4, P3, pb3, P2, pb2, P1, pb1, P0, pb0);
    pe4_kernel<<<NL4, 128>>>(xyz0, out + OFF4);

    pe_mma<1><<<dim3(NL3/32, 2), 256, SMEMB1>>>(k34, x3, x4, xyz0, out + OFF4,
        bh + 1*(size_t)32768, bl + 1*(size_t)32768, coef + 1*(size_t)7*256, out + OFF3);
    pe_mma<1><<<dim3(NL2/32, 2), 256, SMEMB1>>>(k23, x2, x3, xyz0, out + OFF3,
        bh + 2*(size_t)32768, bl + 2*(size_t)32768, coef + 2*(size_t)7*256, out + OFF2);
    pe_mma<2><<<dim3(NL1/64, 2), 256, SMEMB2>>>(k12, x1, x2, xyz0, out + OFF2,
        bh + 3*(size_t)32768, bl + 3*(size_t)32768, coef + 3*(size_t)7*256, out + OFF1);
    pe_mma<2><<<dim3(NL0/64, 2), 256, SMEMB2>>>(idx0, xyz0, x1, xyz0, out + OFF1,
        bh + 4*(size_t)32768, bl + 4*(size_t)32768, coef + 4*(size_t)7*256, out + OFF0);
}